// round 4
// baseline (speedup 1.0000x reference)
#include <cuda_runtime.h>
#include <math.h>

#define BB 8
#define SS 1024
#define DD 1024
#define HH 16
#define HDD 64
#define CDD 512
#define LN_EPS 1e-5f

// ---------------- scratch (device globals; no allocations) ----------------
__device__ float g_tc[4][DD];                 // 16 KB
__device__ float g_qkv[3][BB * SS * DD];      // 96 MB  (Q, K, V modulated-projected)
__device__ float g_x[BB * SS * DD];           // 32 MB  (attention output, pre O-proj)

typedef unsigned long long u64;

__device__ __forceinline__ u64 pack2(float a, float b) {
    u64 r;
    asm("mov.b64 %0, {%1, %2};" : "=l"(r)
        : "r"(__float_as_uint(a)), "r"(__float_as_uint(b)));
    return r;
}
__device__ __forceinline__ float2 unpack2(u64 v) {
    unsigned lo, hi;
    asm("mov.b64 {%0, %1}, %2;" : "=r"(lo), "=r"(hi) : "l"(v));
    return make_float2(__uint_as_float(lo), __uint_as_float(hi));
}
__device__ __forceinline__ void fma2(u64& d, u64 a, u64 b) {
    asm("fma.rn.f32x2 %0, %1, %2, %0;" : "+l"(d) : "l"(a), "l"(b));
}
__device__ __forceinline__ void stcs4(float* p, float4 v) {
    asm volatile("st.global.cs.v4.f32 [%0], {%1,%2,%3,%4};"
                 :: "l"(p), "f"(v.x), "f"(v.y), "f"(v.z), "f"(v.w));
}

// ---------------- kernel 1: tc_p = LayerNorm(code @ wc_w^T + wc_b) ----------------
struct TcParams {
    const float* code;
    const float* wcw[4];
    const float* wcb[4];
    const float* lng[4];
    const float* lnb[4];
};

__global__ __launch_bounds__(256) void tc_kernel(TcParams P) {
    int p = blockIdx.x, t = threadIdx.x;
    __shared__ float sc[CDD];
    __shared__ float raw[DD];
    __shared__ float red[256];
    for (int i = t; i < CDD; i += 256) sc[i] = P.code[i];
    __syncthreads();
    const float* w  = P.wcw[p];
    const float* wb = P.wcb[p];
    for (int k = 0; k < 4; k++) {
        int d = t + k * 256;
        const float4* wr = (const float4*)(w + (size_t)d * CDD);
        const float4* s4 = (const float4*)sc;
        float s = wb[d];
        #pragma unroll 8
        for (int c = 0; c < CDD / 4; c++) {
            float4 wv = wr[c];
            float4 cv = s4[c];
            s += wv.x * cv.x + wv.y * cv.y + wv.z * cv.z + wv.w * cv.w;
        }
        raw[d] = s;
    }
    __syncthreads();
    float ls = 0.f, lq = 0.f;
    for (int k = 0; k < 4; k++) {
        float v = raw[t + k * 256];
        ls += v; lq += v * v;
    }
    red[t] = ls; __syncthreads();
    for (int o = 128; o > 0; o >>= 1) { if (t < o) red[t] += red[t + o]; __syncthreads(); }
    float sum = red[0]; __syncthreads();
    red[t] = lq; __syncthreads();
    for (int o = 128; o > 0; o >>= 1) { if (t < o) red[t] += red[t + o]; __syncthreads(); }
    float sq  = red[0];
    float mu  = sum * (1.f / DD);
    float var = sq * (1.f / DD) - mu * mu;
    float inv = rsqrtf(var + LN_EPS);
    const float* g  = P.lng[p];
    const float* be = P.lnb[p];
    for (int k = 0; k < 4; k++) {
        int d = t + k * 256;
        g_tc[p][d] = (raw[d] - mu) * inv * g[d] + be[d];
    }
}

// ---------------- kernel 2: NT SGEMM  C[r,n] = sum_k (A[r,k]*tc[k]) * W[n,k] + b[n] ----
// tc folded into A at smem-store time; B = raw W (L2-resident, shared by all GEMMs).
// Double-buffered smem: ONE barrier per k-tile.
#define GBM 128
#define GBN 128
#define GBK 16
#define NKT (DD / GBK)

__global__ __launch_bounds__(256, 2) void gemm_kernel(
    const float* __restrict__ a0, const float* __restrict__ a1,
    const float* __restrict__ a2, const float* __restrict__ W,
    const float* __restrict__ bias, float* __restrict__ cout, int mode)
{
    __shared__ float As[2][GBK][GBM];
    __shared__ float Bs[2][GBK][GBN];
    __shared__ float tcs[DD];

    int z = blockIdx.z;
    const float* A;
    const float* tcg;
    float* C;
    if (mode == 0) {
        A   = (z == 0) ? a0 : (z == 1) ? a1 : a2;
        tcg = g_tc[z];
        C   = g_qkv[z];
    } else {
        A   = g_x;
        tcg = g_tc[3];
        C   = cout;
    }
    int tid = threadIdx.x;
    int bm = blockIdx.y * GBM, bn = blockIdx.x * GBN;
    int lr = tid >> 2;            // 0..63
    int lk = (tid & 3) * 4;       // 0,4,8,12
    int ty = tid >> 4, tx = tid & 15;

    // tc -> smem
    {
        float4 t4 = *(const float4*)(tcg + tid * 4);
        *(float4*)(tcs + tid * 4) = t4;
    }

    u64 acc[8][4];
    #pragma unroll
    for (int i = 0; i < 8; i++)
        #pragma unroll
        for (int j = 0; j < 4; j++) acc[i][j] = 0ull;

    const float* Ap = A + (size_t)(bm + lr) * DD;
    const float* Bp = W + (size_t)(bn + lr) * DD;
    float4 pa0 = *(const float4*)(Ap + lk);
    float4 pa1 = *(const float4*)(Ap + (size_t)64 * DD + lk);
    float4 pb0 = *(const float4*)(Bp + lk);
    float4 pb1 = *(const float4*)(Bp + (size_t)64 * DD + lk);
    __syncthreads();   // tcs ready

    // stage tile 0 into buffer 0
    {
        float4 t4 = *(const float4*)(tcs + lk);
        As[0][lk + 0][lr] = pa0.x * t4.x; As[0][lk + 1][lr] = pa0.y * t4.y;
        As[0][lk + 2][lr] = pa0.z * t4.z; As[0][lk + 3][lr] = pa0.w * t4.w;
        As[0][lk + 0][lr + 64] = pa1.x * t4.x; As[0][lk + 1][lr + 64] = pa1.y * t4.y;
        As[0][lk + 2][lr + 64] = pa1.z * t4.z; As[0][lk + 3][lr + 64] = pa1.w * t4.w;
        Bs[0][lk + 0][lr] = pb0.x; Bs[0][lk + 1][lr] = pb0.y;
        Bs[0][lk + 2][lr] = pb0.z; Bs[0][lk + 3][lr] = pb0.w;
        Bs[0][lk + 0][lr + 64] = pb1.x; Bs[0][lk + 1][lr + 64] = pb1.y;
        Bs[0][lk + 2][lr + 64] = pb1.z; Bs[0][lk + 3][lr + 64] = pb1.w;
    }
    __syncthreads();

    #pragma unroll 1
    for (int kt = 0; kt < NKT; kt++) {
        int cur = kt & 1;
        int kn = (kt + 1) * GBK;
        if (kt + 1 < NKT) {
            pa0 = *(const float4*)(Ap + kn + lk);
            pa1 = *(const float4*)(Ap + (size_t)64 * DD + kn + lk);
            pb0 = *(const float4*)(Bp + kn + lk);
            pb1 = *(const float4*)(Bp + (size_t)64 * DD + kn + lk);
        }
        #pragma unroll
        for (int k = 0; k < GBK; k++) {
            float4 av0 = *(const float4*)&As[cur][k][ty * 4];
            float4 av1 = *(const float4*)&As[cur][k][64 + ty * 4];
            ulonglong2 b01 = *(const ulonglong2*)&Bs[cur][k][tx * 4];
            ulonglong2 b23 = *(const ulonglong2*)&Bs[cur][k][64 + tx * 4];
            u64 ap[8];
            ap[0] = pack2(av0.x, av0.x); ap[1] = pack2(av0.y, av0.y);
            ap[2] = pack2(av0.z, av0.z); ap[3] = pack2(av0.w, av0.w);
            ap[4] = pack2(av1.x, av1.x); ap[5] = pack2(av1.y, av1.y);
            ap[6] = pack2(av1.z, av1.z); ap[7] = pack2(av1.w, av1.w);
            #pragma unroll
            for (int i = 0; i < 8; i++) {
                fma2(acc[i][0], ap[i], b01.x);
                fma2(acc[i][1], ap[i], b01.y);
                fma2(acc[i][2], ap[i], b23.x);
                fma2(acc[i][3], ap[i], b23.y);
            }
        }
        if (kt + 1 < NKT) {
            int nxt = cur ^ 1;
            float4 t4 = *(const float4*)(tcs + kn + lk);
            As[nxt][lk + 0][lr] = pa0.x * t4.x; As[nxt][lk + 1][lr] = pa0.y * t4.y;
            As[nxt][lk + 2][lr] = pa0.z * t4.z; As[nxt][lk + 3][lr] = pa0.w * t4.w;
            As[nxt][lk + 0][lr + 64] = pa1.x * t4.x; As[nxt][lk + 1][lr + 64] = pa1.y * t4.y;
            As[nxt][lk + 2][lr + 64] = pa1.z * t4.z; As[nxt][lk + 3][lr + 64] = pa1.w * t4.w;
            Bs[nxt][lk + 0][lr] = pb0.x; Bs[nxt][lk + 1][lr] = pb0.y;
            Bs[nxt][lk + 2][lr] = pb0.z; Bs[nxt][lk + 3][lr] = pb0.w;
            Bs[nxt][lk + 0][lr + 64] = pb1.x; Bs[nxt][lk + 1][lr + 64] = pb1.y;
            Bs[nxt][lk + 2][lr + 64] = pb1.z; Bs[nxt][lk + 3][lr + 64] = pb1.w;
            __syncthreads();
        }
    }

    float4 bv0 = *(const float4*)(bias + bn + tx * 4);
    float4 bv1 = *(const float4*)(bias + bn + 64 + tx * 4);
    #pragma unroll
    for (int i = 0; i < 8; i++) {
        int row = bm + ((i < 4) ? (ty * 4 + i) : (64 + ty * 4 + (i - 4)));
        float2 c0 = unpack2(acc[i][0]), c1 = unpack2(acc[i][1]);
        float2 c2 = unpack2(acc[i][2]), c3 = unpack2(acc[i][3]);
        float4 o0 = make_float4(c0.x + bv0.x, c0.y + bv0.y, c1.x + bv0.z, c1.y + bv0.w);
        float4 o1 = make_float4(c2.x + bv1.x, c2.y + bv1.y, c3.x + bv1.z, c3.y + bv1.w);
        *(float4*)(C + (size_t)row * DD + bn + tx * 4)      = o0;
        *(float4*)(C + (size_t)row * DD + bn + 64 + tx * 4) = o1;
    }
}

// ---------------- kernel 3: fused attention, two-pass streaming ----------------
// Per block: (b, h, 32 rows). Pass 1: row sums of exp(E) (E recomputed, never stored
// globally). Pass 2: recompute E, f = uj*e/(c + uj*e) with c = 1e-6*sum/ui (exact
// algebra of a/(eps+a)), streaming-store attention, accumulate AV.
#define JT   128
#define KSTR 132
#define VSTR 72
#define FSTR 132
#define QSTR 68
#define SM_KS 0
#define SM_VS (64 * KSTR)                        // 8448
#define SM_FS (SM_VS + JT * VSTR)                // +9216
#define SM_QS (SM_FS + 32 * FSTR)                // +4224
#define SM_UJ (SM_QS + 32 * QSTR)                // +2176
#define SM_CR (SM_UJ + SS)                       // +1024
#define AT_SMEM_FLOATS (SM_CR + 32)
#define AT_SMEM_BYTES  (AT_SMEM_FLOATS * 4)      // 100,608 B -> 2 CTAs/SM

__global__ __launch_bounds__(256, 2) void attn_kernel(const float* __restrict__ u,
                                                      float* __restrict__ att) {
    extern __shared__ float sm[];
    float* Ks   = sm + SM_KS;    // [64][KSTR]  (d-major)
    float* Vs   = sm + SM_VS;    // [JT][VSTR]
    float* Fs   = sm + SM_FS;    // [32][FSTR]
    float* Qs   = sm + SM_QS;    // [32][QSTR]
    float* usj  = sm + SM_UJ;    // [1024]
    float* crow = sm + SM_CR;    // [32]

    int tid = threadIdx.x;
    int i0 = blockIdx.x * 32;
    int h  = blockIdx.y;
    int b  = blockIdx.z;
    const float* Qg = g_qkv[0] + (size_t)b * SS * DD + h * HDD;
    const float* Kg = g_qkv[1] + (size_t)b * SS * DD + h * HDD;
    const float* Vg = g_qkv[2] + (size_t)b * SS * DD + h * HDD;

    // load Q tile + u vector
    for (int i = tid; i < 512; i += 256) {
        int r = i >> 4, dq = (i & 15) * 4;
        float4 v = *(const float4*)(Qg + (size_t)(i0 + r) * DD + dq);
        float* q = Qs + r * QSTR + dq;
        q[0] = v.x; q[1] = v.y; q[2] = v.z; q[3] = v.w;
    }
    for (int i = tid; i < SS; i += 256) usj[i] = u[b * SS + i];

    int r0 = (tid >> 4) * 2, c0 = (tid & 15) * 8;

    // ---- pass 1: row sums of exp(E) ----
    float lsum0 = 0.f, lsum1 = 0.f;
    for (int jt = 0; jt < 8; jt++) {
        int j0 = jt * JT;
        __syncthreads();
        #pragma unroll
        for (int i = 0; i < 8; i++) {
            int idx = tid + i * 256;
            int j = idx >> 4, dq = (idx & 15) * 4;
            float4 v = *(const float4*)(Kg + (size_t)(j0 + j) * DD + dq);
            Ks[(dq + 0) * KSTR + j] = v.x; Ks[(dq + 1) * KSTR + j] = v.y;
            Ks[(dq + 2) * KSTR + j] = v.z; Ks[(dq + 3) * KSTR + j] = v.w;
        }
        __syncthreads();
        u64 acc[2][4] = {{0ull,0ull,0ull,0ull},{0ull,0ull,0ull,0ull}};
        #pragma unroll
        for (int d = 0; d < 64; d += 4) {
            float4 qa = *(const float4*)(Qs + r0 * QSTR + d);
            float4 qb = *(const float4*)(Qs + (r0 + 1) * QSTR + d);
            #pragma unroll
            for (int dd = 0; dd < 4; dd++) {
                float qav = (&qa.x)[dd], qbv = (&qb.x)[dd];
                u64 p0 = pack2(qav, qav), p1 = pack2(qbv, qbv);
                ulonglong2 k01 = *(const ulonglong2*)(Ks + (d + dd) * KSTR + c0);
                ulonglong2 k23 = *(const ulonglong2*)(Ks + (d + dd) * KSTR + c0 + 4);
                fma2(acc[0][0], p0, k01.x); fma2(acc[0][1], p0, k01.y);
                fma2(acc[0][2], p0, k23.x); fma2(acc[0][3], p0, k23.y);
                fma2(acc[1][0], p1, k01.x); fma2(acc[1][1], p1, k01.y);
                fma2(acc[1][2], p1, k23.x); fma2(acc[1][3], p1, k23.y);
            }
        }
        #pragma unroll
        for (int q = 0; q < 4; q++) {
            float2 e0 = unpack2(acc[0][q]);
            float2 e1 = unpack2(acc[1][q]);
            lsum0 += __expf(e0.x * 0.125f) + __expf(e0.y * 0.125f);
            lsum1 += __expf(e1.x * 0.125f) + __expf(e1.y * 0.125f);
        }
    }
    // reduce over the 16 lanes sharing (r0, r0+1)
    #pragma unroll
    for (int o = 8; o > 0; o >>= 1) {
        lsum0 += __shfl_xor_sync(0xffffffffu, lsum0, o);
        lsum1 += __shfl_xor_sync(0xffffffffu, lsum1, o);
    }
    if ((tid & 15) == 0) {
        crow[r0]     = 1e-6f * lsum0 / usj[i0 + r0];
        crow[r0 + 1] = 1e-6f * lsum1 / usj[i0 + r0 + 1];
    }

    // ---- pass 2: recompute E, write attention, accumulate AV ----
    int rr2 = tid >> 3;
    int hd0 = (tid & 7) * 8;
    u64 avacc[4] = {0ull, 0ull, 0ull, 0ull};
    for (int jt = 0; jt < 8; jt++) {
        int j0 = jt * JT;
        __syncthreads();   // prev AV done reading Vs/Fs; crow visible on first iter
        #pragma unroll
        for (int i = 0; i < 8; i++) {
            int idx = tid + i * 256;
            int j = idx >> 4, dq = (idx & 15) * 4;
            float4 kv = *(const float4*)(Kg + (size_t)(j0 + j) * DD + dq);
            Ks[(dq + 0) * KSTR + j] = kv.x; Ks[(dq + 1) * KSTR + j] = kv.y;
            Ks[(dq + 2) * KSTR + j] = kv.z; Ks[(dq + 3) * KSTR + j] = kv.w;
            float4 vv = *(const float4*)(Vg + (size_t)(j0 + j) * DD + dq);
            float* vp = Vs + j * VSTR + dq;
            vp[0] = vv.x; vp[1] = vv.y; vp[2] = vv.z; vp[3] = vv.w;
        }
        __syncthreads();
        u64 acc[2][4] = {{0ull,0ull,0ull,0ull},{0ull,0ull,0ull,0ull}};
        #pragma unroll
        for (int d = 0; d < 64; d += 4) {
            float4 qa = *(const float4*)(Qs + r0 * QSTR + d);
            float4 qb = *(const float4*)(Qs + (r0 + 1) * QSTR + d);
            #pragma unroll
            for (int dd = 0; dd < 4; dd++) {
                float qav = (&qa.x)[dd], qbv = (&qb.x)[dd];
                u64 p0 = pack2(qav, qav), p1 = pack2(qbv, qbv);
                ulonglong2 k01 = *(const ulonglong2*)(Ks + (d + dd) * KSTR + c0);
                ulonglong2 k23 = *(const ulonglong2*)(Ks + (d + dd) * KSTR + c0 + 4);
                fma2(acc[0][0], p0, k01.x); fma2(acc[0][1], p0, k01.y);
                fma2(acc[0][2], p0, k23.x); fma2(acc[0][3], p0, k23.y);
                fma2(acc[1][0], p1, k01.x); fma2(acc[1][1], p1, k01.y);
                fma2(acc[1][2], p1, k23.x); fma2(acc[1][3], p1, k23.y);
            }
        }
        float4 uj0 = *(const float4*)(usj + j0 + c0);
        float4 uj1 = *(const float4*)(usj + j0 + c0 + 4);
        #pragma unroll
        for (int rr = 0; rr < 2; rr++) {
            float cr = crow[r0 + rr];
            float2 e0 = unpack2(acc[rr][0]), e1 = unpack2(acc[rr][1]);
            float2 e2 = unpack2(acc[rr][2]), e3 = unpack2(acc[rr][3]);
            float t0 = uj0.x * __expf(e0.x * 0.125f);
            float t1 = uj0.y * __expf(e0.y * 0.125f);
            float t2 = uj0.z * __expf(e1.x * 0.125f);
            float t3 = uj0.w * __expf(e1.y * 0.125f);
            float t4 = uj1.x * __expf(e2.x * 0.125f);
            float t5 = uj1.y * __expf(e2.y * 0.125f);
            float t6 = uj1.z * __expf(e3.x * 0.125f);
            float t7 = uj1.w * __expf(e3.y * 0.125f);
            float4 fa = make_float4(__fdividef(t0, cr + t0), __fdividef(t1, cr + t1),
                                    __fdividef(t2, cr + t2), __fdividef(t3, cr + t3));
            float4 fb = make_float4(__fdividef(t4, cr + t4), __fdividef(t5, cr + t5),
                                    __fdividef(t6, cr + t6), __fdividef(t7, cr + t7));
            float* fp = Fs + (r0 + rr) * FSTR + c0;
            *(float4*)fp       = fa;
            *(float4*)(fp + 4) = fb;
            float* go = att + (((size_t)(b * HH + h)) * SS + (i0 + r0 + rr)) * SS + j0 + c0;
            stcs4(go, fa);
            stcs4(go + 4, fb);
        }
        __syncthreads();   // Fs ready
        const float* er = Fs + rr2 * FSTR;
        #pragma unroll 4
        for (int j = 0; j < JT; j++) {
            float f = er[j];
            u64 fp2 = pack2(f, f);
            ulonglong2 v01 = *(const ulonglong2*)(Vs + j * VSTR + hd0);
            ulonglong2 v23 = *(const ulonglong2*)(Vs + j * VSTR + hd0 + 4);
            fma2(avacc[0], fp2, v01.x); fma2(avacc[1], fp2, v01.y);
            fma2(avacc[2], fp2, v23.x); fma2(avacc[3], fp2, v23.y);
        }
    }
    float2 x0 = unpack2(avacc[0]), x1 = unpack2(avacc[1]);
    float2 x2 = unpack2(avacc[2]), x3 = unpack2(avacc[3]);
    float* xo = g_x + ((size_t)b * SS + i0 + rr2) * DD + h * HDD + hd0;
    *(float4*)xo       = make_float4(x0.x, x0.y, x1.x, x1.y);
    *(float4*)(xo + 4) = make_float4(x2.x, x2.y, x3.x, x3.y);
}

// ---------------- launch ----------------
extern "C" void kernel_launch(void* const* d_in, const int* in_sizes, int n_in,
                              void* d_out, int out_size) {
    const float* query = (const float*)d_in[0];
    const float* key   = (const float*)d_in[1];
    const float* value = (const float*)d_in[2];
    const float* u     = (const float*)d_in[3];
    const float* code  = (const float*)d_in[4];
    const float* W     = (const float*)d_in[5];
    const float* bias  = (const float*)d_in[6];

    TcParams tp;
    tp.code = code;
    for (int p = 0; p < 4; p++) {
        tp.wcw[p] = (const float*)d_in[7 + 4 * p];
        tp.wcb[p] = (const float*)d_in[8 + 4 * p];
        tp.lng[p] = (const float*)d_in[9 + 4 * p];
        tp.lnb[p] = (const float*)d_in[10 + 4 * p];
    }

    // 1) transformed codes (tiny)
    tc_kernel<<<4, 256>>>(tp);
    // 2) Q/K/V projections (tc folded into A; B = W, L2-resident)
    gemm_kernel<<<dim3(DD / GBN, BB * SS / GBM, 3), 256>>>(query, key, value, W, bias, nullptr, 0);
    // 3) fused attention -> attention region of d_out (streaming) + g_x
    cudaFuncSetAttribute(attn_kernel, cudaFuncAttributeMaxDynamicSharedMemorySize, AT_SMEM_BYTES);
    float* att = (float*)d_out + (size_t)BB * SS * DD;
    attn_kernel<<<dim3(SS / 32, HH, BB), 256, AT_SMEM_BYTES>>>(u, att);
    // 4) output projection -> x region of d_out
    gemm_kernel<<<dim3(DD / GBN, BB * SS / GBM, 1), 256>>>(nullptr, nullptr, nullptr, W, bias, (float*)d_out, 1);
}

// round 8
// speedup vs baseline: 4.3812x; 4.3812x over previous
#include <cuda_runtime.h>
#include <cuda_bf16.h>
#include <math.h>
#include <cstdint>

#define BB 8
#define SS 1024
#define DD 1024
#define HH 16
#define HDD 64
#define CDD 512
#define LN_EPS 1e-5f

typedef unsigned short ushort_t;
typedef unsigned int u32;

// ---------------- scratch (device globals; no allocations) ----------------
__device__ float    g_tc[4][DD];                    // 16 KB
__device__ float    g_v32[BB * SS * DD];            // 32 MB  (projected V, f32, for colsum)
__device__ float    g_x[BB * SS * DD];              // 32 MB  (attention out, pre O-proj)
__device__ ushort_t g_hi[4][BB * SS * DD];          // 64 MB  (split-bf16 hi of GEMM A operands)
__device__ ushort_t g_lo[4][BB * SS * DD];          // 64 MB
__device__ ushort_t g_whi[DD * DD];                 // 2 MB
__device__ ushort_t g_wlo[DD * DD];                 // 2 MB
__device__ ushort_t g_qkvh[3][BB * SS * DD];        // 48 MB  (projected Q,K,V bf16)
__device__ float    g_vsum[BB * HH * HDD];          // 32 KB  (colsum of V per (b,h))

// ---------------- helpers ----------------
__device__ __forceinline__ void mma_bf16(float4& d, const u32 a[4], u32 b0, u32 b1) {
    asm volatile("mma.sync.aligned.m16n8k16.row.col.f32.bf16.bf16.f32 "
                 "{%0,%1,%2,%3}, {%4,%5,%6,%7}, {%8,%9}, {%0,%1,%2,%3};"
                 : "+f"(d.x), "+f"(d.y), "+f"(d.z), "+f"(d.w)
                 : "r"(a[0]), "r"(a[1]), "r"(a[2]), "r"(a[3]), "r"(b0), "r"(b1));
}
__device__ __forceinline__ void stcs2(float* p, float a, float b) {
    asm volatile("st.global.cs.v2.f32 [%0], {%1,%2};" :: "l"(p), "f"(a), "f"(b));
}
__device__ __forceinline__ u32 pack_bf16x2(float a, float b) {
    return (u32)__bfloat16_as_ushort(__float2bfloat16(a))
         | ((u32)__bfloat16_as_ushort(__float2bfloat16(b)) << 16);
}

// ---------------- kernel 1: tc_p = LayerNorm(code @ wc_w^T + wc_b) ----------------
struct TcParams {
    const float* code;
    const float* wcw[4];
    const float* wcb[4];
    const float* lng[4];
    const float* lnb[4];
};

__global__ __launch_bounds__(256) void tc_kernel(TcParams P) {
    int p = blockIdx.x, t = threadIdx.x;
    __shared__ float sc[CDD];
    __shared__ float raw[DD];
    __shared__ float red[256];
    for (int i = t; i < CDD; i += 256) sc[i] = P.code[i];
    __syncthreads();
    const float* w  = P.wcw[p];
    const float* wb = P.wcb[p];
    for (int k = 0; k < 4; k++) {
        int d = t + k * 256;
        const float4* wr = (const float4*)(w + (size_t)d * CDD);
        const float4* s4 = (const float4*)sc;
        float s = wb[d];
        #pragma unroll 8
        for (int c = 0; c < CDD / 4; c++) {
            float4 wv = wr[c];
            float4 cv = s4[c];
            s += wv.x * cv.x + wv.y * cv.y + wv.z * cv.z + wv.w * cv.w;
        }
        raw[d] = s;
    }
    __syncthreads();
    float ls = 0.f, lq = 0.f;
    for (int k = 0; k < 4; k++) {
        float v = raw[t + k * 256];
        ls += v; lq += v * v;
    }
    red[t] = ls; __syncthreads();
    for (int o = 128; o > 0; o >>= 1) { if (t < o) red[t] += red[t + o]; __syncthreads(); }
    float sum = red[0]; __syncthreads();
    red[t] = lq; __syncthreads();
    for (int o = 128; o > 0; o >>= 1) { if (t < o) red[t] += red[t + o]; __syncthreads(); }
    float sq  = red[0];
    float mu  = sum * (1.f / DD);
    float var = sq * (1.f / DD) - mu * mu;
    float inv = rsqrtf(var + LN_EPS);
    const float* g  = P.lng[p];
    const float* be = P.lnb[p];
    for (int k = 0; k < 4; k++) {
        int d = t + k * 256;
        g_tc[p][d] = (raw[d] - mu) * inv * g[d] + be[d];
    }
}

// ---------------- conversions: fp32 (x tc) -> split bf16 (hi, lo) ----------------
__device__ __forceinline__ void split_store(float4 a, ushort_t* hi, ushort_t* lo, size_t i4) {
    unsigned hx = __bfloat16_as_ushort(__float2bfloat16(a.x));
    unsigned hy = __bfloat16_as_ushort(__float2bfloat16(a.y));
    unsigned hz = __bfloat16_as_ushort(__float2bfloat16(a.z));
    unsigned hw = __bfloat16_as_ushort(__float2bfloat16(a.w));
    float rx = a.x - __bfloat162float(__ushort_as_bfloat16((ushort_t)hx));
    float ry = a.y - __bfloat162float(__ushort_as_bfloat16((ushort_t)hy));
    float rz = a.z - __bfloat162float(__ushort_as_bfloat16((ushort_t)hz));
    float rw = a.w - __bfloat162float(__ushort_as_bfloat16((ushort_t)hw));
    unsigned lx = __bfloat16_as_ushort(__float2bfloat16(rx));
    unsigned ly = __bfloat16_as_ushort(__float2bfloat16(ry));
    unsigned lz = __bfloat16_as_ushort(__float2bfloat16(rz));
    unsigned lw = __bfloat16_as_ushort(__float2bfloat16(rw));
    ((uint2*)hi)[i4] = make_uint2(hx | (hy << 16), hz | (hw << 16));
    ((uint2*)lo)[i4] = make_uint2(lx | (ly << 16), lz | (lw << 16));
}

__global__ __launch_bounds__(256) void conv_in_kernel(const float* __restrict__ q,
                                                      const float* __restrict__ k,
                                                      const float* __restrict__ v) {
    int z = blockIdx.y;
    const float* in = (z == 0) ? q : (z == 1) ? k : v;
    size_t i4 = (size_t)blockIdx.x * 256 + threadIdx.x;
    float4 a = ((const float4*)in)[i4];
    int kc = (int)((i4 * 4) & (DD - 1));
    float4 t = *(const float4*)&g_tc[z][kc];
    a.x *= t.x; a.y *= t.y; a.z *= t.z; a.w *= t.w;
    split_store(a, g_hi[z], g_lo[z], i4);
}

__global__ __launch_bounds__(256) void conv_x_kernel() {
    size_t i4 = (size_t)blockIdx.x * 256 + threadIdx.x;
    float4 a = ((const float4*)g_x)[i4];
    int kc = (int)((i4 * 4) & (DD - 1));
    float4 t = *(const float4*)&g_tc[3][kc];
    a.x *= t.x; a.y *= t.y; a.z *= t.z; a.w *= t.w;
    split_store(a, g_hi[3], g_lo[3], i4);
}

__global__ __launch_bounds__(256) void conv_w_kernel(const float* __restrict__ W) {
    size_t i4 = (size_t)blockIdx.x * 256 + threadIdx.x;
    float4 a = ((const float4*)W)[i4];
    split_store(a, g_whi, g_wlo, i4);
}

// ---------------- vsum: colsum of projected V per (b,h) ----------------
__global__ __launch_bounds__(512) void vsum_kernel() {
    int bh = blockIdx.x;
    int b = bh >> 4, h = bh & 15;
    int tid = threadIdx.x;
    int d = tid & 63, jg = tid >> 6;
    const float* Vp = g_v32 + (size_t)b * SS * DD + h * HDD + d;
    float s = 0.f;
    for (int j = jg * 128; j < jg * 128 + 128; j++) s += Vp[(size_t)j * DD];
    __shared__ float rs[512];
    rs[tid] = s;
    __syncthreads();
    if (tid < 64) {
        float t = 0.f;
        #pragma unroll
        for (int k = 0; k < 8; k++) t += rs[k * 64 + tid];
        g_vsum[bh * 64 + tid] = t;
    }
}

// ---------------- projection GEMM on HMMA: C[r,n] = sum_k A[r,k]*W[n,k] + b[n] -------
// split-bf16 3-term. Block 128x128, 8 warps (warp tile 64x32), K chunk 32.
#define PST 40        // smem row stride (bf16 elems); conflict-free fragment reads

__global__ __launch_bounds__(256, 2) void gemm_mma_kernel(const float* __restrict__ bias,
                                                          float* __restrict__ cout, int zbase) {
    __shared__ __align__(16) ushort_t Ah[128 * PST];
    __shared__ __align__(16) ushort_t Al[128 * PST];
    __shared__ __align__(16) ushort_t Bh[128 * PST];
    __shared__ __align__(16) ushort_t Bl[128 * PST];
    __shared__ float sbias[128];

    int z = blockIdx.z + zbase;
    const ushort_t* Ahg = g_hi[z];
    const ushort_t* Alg = g_lo[z];
    float*    Cf = (z == 2) ? g_v32 : ((z == 3) ? cout : nullptr);
    ushort_t* Cb = (z < 3) ? g_qkvh[z] : nullptr;

    int tid = threadIdx.x;
    int wid = tid >> 5, lane = tid & 31;
    int g = lane >> 2, tig = lane & 3;
    int wr = wid & 1, wc = wid >> 1;           // m: 64*wr, n: 32*wc
    int bm = blockIdx.y * 128, bn = blockIdx.x * 128;

    float4 acc[4][4];
    #pragma unroll
    for (int i = 0; i < 4; i++)
        #pragma unroll
        for (int j = 0; j < 4; j++) acc[i][j] = make_float4(0.f, 0.f, 0.f, 0.f);

    if (tid < 128) sbias[tid] = bias[bn + tid];

    #pragma unroll 1
    for (int kc = 0; kc < DD / 32; kc++) {
        __syncthreads();
        #pragma unroll
        for (int t = 0; t < 2; t++) {
            int i2 = tid + t * 256;               // 0..511
            int row = i2 >> 2, c8 = (i2 & 3) * 8;
            size_t gA = (size_t)(bm + row) * DD + kc * 32 + c8;
            size_t gB = (size_t)(bn + row) * DD + kc * 32 + c8;
            *(uint4*)&Ah[row * PST + c8] = *(const uint4*)&Ahg[gA];
            *(uint4*)&Al[row * PST + c8] = *(const uint4*)&Alg[gA];
            *(uint4*)&Bh[row * PST + c8] = *(const uint4*)&g_whi[gB];
            *(uint4*)&Bl[row * PST + c8] = *(const uint4*)&g_wlo[gB];
        }
        __syncthreads();
        #pragma unroll
        for (int ks = 0; ks < 2; ks++) {
            int k0 = ks * 16;
            u32 ah[4][4], al[4][4];
            #pragma unroll
            for (int mf = 0; mf < 4; mf++) {
                int r0 = wr * 64 + mf * 16 + g;
                const ushort_t* p0 = Ah + r0 * PST + k0 + 2 * tig;
                const ushort_t* p1 = p0 + 8 * PST;
                ah[mf][0] = *(const u32*)p0;       ah[mf][1] = *(const u32*)p1;
                ah[mf][2] = *(const u32*)(p0 + 8); ah[mf][3] = *(const u32*)(p1 + 8);
                const ushort_t* q0 = Al + r0 * PST + k0 + 2 * tig;
                const ushort_t* q1 = q0 + 8 * PST;
                al[mf][0] = *(const u32*)q0;       al[mf][1] = *(const u32*)q1;
                al[mf][2] = *(const u32*)(q0 + 8); al[mf][3] = *(const u32*)(q1 + 8);
            }
            #pragma unroll
            for (int nf = 0; nf < 4; nf++) {
                int n0 = wc * 32 + nf * 8 + g;
                const ushort_t* bp = Bh + n0 * PST + k0 + 2 * tig;
                u32 bh0 = *(const u32*)bp, bh1 = *(const u32*)(bp + 8);
                const ushort_t* lp = Bl + n0 * PST + k0 + 2 * tig;
                u32 bl0 = *(const u32*)lp, bl1 = *(const u32*)(lp + 8);
                #pragma unroll
                for (int mf = 0; mf < 4; mf++) {
                    mma_bf16(acc[mf][nf], ah[mf], bh0, bh1);
                    mma_bf16(acc[mf][nf], ah[mf], bl0, bl1);
                    mma_bf16(acc[mf][nf], al[mf], bh0, bh1);
                }
            }
        }
    }

    // epilogue
    #pragma unroll
    for (int mf = 0; mf < 4; mf++) {
        int r0 = bm + wr * 64 + mf * 16 + g;
        #pragma unroll
        for (int nf = 0; nf < 4; nf++) {
            int cl = wc * 32 + nf * 8 + 2 * tig;
            int c  = bn + cl;
            float2 b2 = *(const float2*)&sbias[cl];
            float4 v = acc[mf][nf];
            float o0x = v.x + b2.x, o0y = v.y + b2.y;
            float o1x = v.z + b2.x, o1y = v.w + b2.y;
            if (Cf) {
                *(float2*)&Cf[(size_t)r0 * DD + c]       = make_float2(o0x, o0y);
                *(float2*)&Cf[(size_t)(r0 + 8) * DD + c] = make_float2(o1x, o1y);
            }
            if (Cb) {
                *(u32*)&Cb[(size_t)r0 * DD + c]       = pack_bf16x2(o0x, o0y);
                *(u32*)&Cb[(size_t)(r0 + 8) * DD + c] = pack_bf16x2(o1x, o1y);
            }
        }
    }
}

// ---------------- fused attention on HMMA ----------------
// Block: (b, h, 64 q-rows). Pass 1: rowsums of exp(E/8) via bf16 QK MMA.
// Pass 2: recompute E, f = t/(c+t) (t = u_j exp(E/8), c = 1e-6*sum/u_i),
// streaming-store f, store G = 1-f bf16, x = colsum(V) - G@V via MMA.
#define QS2 72
#define KS2 72
#define VS2 132
#define GS2 132
#define AT_Q 0
#define AT_K (AT_Q + 64 * QS2)
#define AT_V (AT_K + 128 * KS2)
#define AT_G (AT_V + 64 * VS2)
#define AT_USH (AT_G + 64 * GS2)                  // total ushort count
#define AT_SMEM_BYTES (AT_USH * 2 + (SS + 64 + 128) * 4)

__global__ __launch_bounds__(256, 2) void attn_mma_kernel(const float* __restrict__ u,
                                                          float* __restrict__ att) {
    extern __shared__ __align__(16) char smemc[];
    ushort_t* Qs  = (ushort_t*)smemc + AT_Q;   // [64][QS2]
    ushort_t* Ks  = (ushort_t*)smemc + AT_K;   // [128][KS2]
    ushort_t* Vsh = (ushort_t*)smemc + AT_V;   // [64][VS2]  (V^T: [d][j])
    ushort_t* Gs  = (ushort_t*)smemc + AT_G;   // [64][GS2]
    float* usj  = (float*)(smemc + AT_USH * 2);     // [1024]
    float* crow = usj + SS;                         // [64]
    float* red  = crow + 64;                        // [128]

    int tid = threadIdx.x;
    int wid = tid >> 5, lane = tid & 31;
    int g = lane >> 2, tig = lane & 3;
    int wr = wid & 3, wc = wid >> 2;         // QK: rows 16*wr, cols 64*wc
    int i0 = blockIdx.x * 64;
    int h  = blockIdx.y;
    int b  = blockIdx.z;
    const ushort_t* Qg = g_qkvh[0] + (size_t)b * SS * DD + h * HDD;
    const ushort_t* Kg = g_qkvh[1] + (size_t)b * SS * DD + h * HDD;
    const ushort_t* Vg = g_qkvh[2] + (size_t)b * SS * DD + h * HDD;

    // load Q tile + u
    #pragma unroll
    for (int t = 0; t < 2; t++) {
        int i = tid + t * 256;               // 0..511
        int row = i >> 3, c8 = (i & 7) * 8;
        *(uint4*)&Qs[row * QS2 + c8] = *(const uint4*)&Qg[(size_t)(i0 + row) * DD + c8];
    }
    for (int i = tid; i < SS; i += 256) usj[i] = u[b * SS + i];

    // ---- pass 1: rowsums of exp(E/8) ----
    float s0 = 0.f, s1 = 0.f;
    #pragma unroll 1
    for (int jt = 0; jt < 8; jt++) {
        int j0 = jt * 128;
        __syncthreads();
        #pragma unroll
        for (int t = 0; t < 4; t++) {
            int i = tid + t * 256;
            int row = i >> 3, c8 = (i & 7) * 8;
            *(uint4*)&Ks[row * KS2 + c8] = *(const uint4*)&Kg[(size_t)(j0 + row) * DD + c8];
        }
        __syncthreads();
        float4 eacc[8];
        #pragma unroll
        for (int nf = 0; nf < 8; nf++) eacc[nf] = make_float4(0.f, 0.f, 0.f, 0.f);
        #pragma unroll
        for (int ks = 0; ks < 4; ks++) {
            int k0 = ks * 16;
            u32 a[4];
            const ushort_t* p0 = Qs + (16 * wr + g) * QS2 + k0 + 2 * tig;
            const ushort_t* p1 = p0 + 8 * QS2;
            a[0] = *(const u32*)p0;       a[1] = *(const u32*)p1;
            a[2] = *(const u32*)(p0 + 8); a[3] = *(const u32*)(p1 + 8);
            #pragma unroll
            for (int nf = 0; nf < 8; nf++) {
                const ushort_t* q0 = Ks + (64 * wc + nf * 8 + g) * KS2 + k0 + 2 * tig;
                mma_bf16(eacc[nf], a, *(const u32*)q0, *(const u32*)(q0 + 8));
            }
        }
        #pragma unroll
        for (int nf = 0; nf < 8; nf++) {
            float4 e = eacc[nf];
            s0 += __expf(e.x * 0.125f) + __expf(e.y * 0.125f);
            s1 += __expf(e.z * 0.125f) + __expf(e.w * 0.125f);
        }
    }
    s0 += __shfl_xor_sync(0xffffffffu, s0, 1);
    s0 += __shfl_xor_sync(0xffffffffu, s0, 2);
    s1 += __shfl_xor_sync(0xffffffffu, s1, 1);
    s1 += __shfl_xor_sync(0xffffffffu, s1, 2);
    if (tig == 0) {
        red[wc * 64 + 16 * wr + g]     = s0;
        red[wc * 64 + 16 * wr + g + 8] = s1;
    }
    __syncthreads();
    if (tid < 64) crow[tid] = 1e-6f * (red[tid] + red[64 + tid]) / usj[i0 + tid];

    // ---- pass 2: recompute E, write f, G = 1-f, x += G@V ----
    int wr2 = wid & 3, wc2 = wid >> 2;       // GV: rows 16*wr2, cols 32*wc2
    float4 xacc[4];
    #pragma unroll
    for (int nf = 0; nf < 4; nf++) xacc[nf] = make_float4(0.f, 0.f, 0.f, 0.f);

    #pragma unroll 1
    for (int jt = 0; jt < 8; jt++) {
        int j0 = jt * 128;
        __syncthreads();  // crow visible (1st iter); prev GV done with Ks/Vsh/Gs
        #pragma unroll
        for (int t = 0; t < 4; t++) {
            int i = tid + t * 256;
            int row = i >> 3, c8 = (i & 7) * 8;
            *(uint4*)&Ks[row * KS2 + c8] = *(const uint4*)&Kg[(size_t)(j0 + row) * DD + c8];
        }
        #pragma unroll
        for (int t = 0; t < 16; t++) {
            int i = tid + t * 256;                 // 0..4095
            int dp = i & 31, j = i >> 5;           // d-pair, j-local
            u32 vh = *(const u32*)&Vg[(size_t)(j0 + j) * DD + 2 * dp];
            Vsh[(2 * dp) * VS2 + j]     = (ushort_t)(vh & 0xffffu);
            Vsh[(2 * dp + 1) * VS2 + j] = (ushort_t)(vh >> 16);
        }
        __syncthreads();
        // QK
        float4 eacc[8];
        #pragma unroll
        for (int nf = 0; nf < 8; nf++) eacc[nf] = make_float4(0.f, 0.f, 0.f, 0.f);
        #pragma unroll
        for (int ks = 0; ks < 4; ks++) {
            int k0 = ks * 16;
            u32 a[4];
            const ushort_t* p0 = Qs + (16 * wr + g) * QS2 + k0 + 2 * tig;
            const ushort_t* p1 = p0 + 8 * QS2;
            a[0] = *(const u32*)p0;       a[1] = *(const u32*)p1;
            a[2] = *(const u32*)(p0 + 8); a[3] = *(const u32*)(p1 + 8);
            #pragma unroll
            for (int nf = 0; nf < 8; nf++) {
                const ushort_t* q0 = Ks + (64 * wc + nf * 8 + g) * KS2 + k0 + 2 * tig;
                mma_bf16(eacc[nf], a, *(const u32*)q0, *(const u32*)(q0 + 8));
            }
        }
        // f + streaming store + G
        int ra = 16 * wr + g, rb = ra + 8;
        float ca = crow[ra], cb = crow[rb];
        float* atta = att + (((size_t)(b * HH + h)) * SS + (i0 + ra)) * SS + j0;
        float* attb = att + (((size_t)(b * HH + h)) * SS + (i0 + rb)) * SS + j0;
        #pragma unroll
        for (int nf = 0; nf < 8; nf++) {
            int col = 64 * wc + 8 * nf + 2 * tig;
            float2 uj = *(const float2*)&usj[j0 + col];
            float4 e = eacc[nf];
            float t0 = uj.x * __expf(e.x * 0.125f);
            float t1 = uj.y * __expf(e.y * 0.125f);
            float t2 = uj.x * __expf(e.z * 0.125f);
            float t3 = uj.y * __expf(e.w * 0.125f);
            float f0 = __fdividef(t0, ca + t0);
            float f1 = __fdividef(t1, ca + t1);
            float f2 = __fdividef(t2, cb + t2);
            float f3 = __fdividef(t3, cb + t3);
            stcs2(atta + col, f0, f1);
            stcs2(attb + col, f2, f3);
            *(u32*)&Gs[ra * GS2 + col] = pack_bf16x2(1.f - f0, 1.f - f1);
            *(u32*)&Gs[rb * GS2 + col] = pack_bf16x2(1.f - f2, 1.f - f3);
        }
        __syncthreads();  // Gs ready
        // GV: x[64][64] -= wait: accumulate G@V, subtract at end
        #pragma unroll
        for (int ks = 0; ks < 8; ks++) {
            int k0 = ks * 16;
            u32 a[4];
            const ushort_t* p0 = Gs + (16 * wr2 + g) * GS2 + k0 + 2 * tig;
            const ushort_t* p1 = p0 + 8 * GS2;
            a[0] = *(const u32*)p0;       a[1] = *(const u32*)p1;
            a[2] = *(const u32*)(p0 + 8); a[3] = *(const u32*)(p1 + 8);
            #pragma unroll
            for (int nf = 0; nf < 4; nf++) {
                const ushort_t* q0 = Vsh + (32 * wc2 + nf * 8 + g) * VS2 + k0 + 2 * tig;
                mma_bf16(xacc[nf], a, *(const u32*)q0, *(const u32*)(q0 + 8));
            }
        }
    }

    // epilogue: x = colsum(V) - G@V
    {
        const float* vs = g_vsum + (b * HH + h) * HDD;
        int ra = 16 * wr2 + g, rb = ra + 8;
        #pragma unroll
        for (int nf = 0; nf < 4; nf++) {
            int col = 32 * wc2 + 8 * nf + 2 * tig;
            float2 v2 = *(const float2*)&vs[col];
            float4 xv = xacc[nf];
            float* xa = g_x + ((size_t)b * SS + i0 + ra) * DD + h * HDD + col;
            float* xb = g_x + ((size_t)b * SS + i0 + rb) * DD + h * HDD + col;
            *(float2*)xa = make_float2(v2.x - xv.x, v2.y - xv.y);
            *(float2*)xb = make_float2(v2.x - xv.z, v2.y - xv.w);
        }
    }
}

// ---------------- launch ----------------
extern "C" void kernel_launch(void* const* d_in, const int* in_sizes, int n_in,
                              void* d_out, int out_size) {
    const float* query = (const float*)d_in[0];
    const float* key   = (const float*)d_in[1];
    const float* value = (const float*)d_in[2];
    const float* u     = (const float*)d_in[3];
    const float* code  = (const float*)d_in[4];
    const float* W     = (const float*)d_in[5];
    const float* bias  = (const float*)d_in[6];

    TcParams tp;
    tp.code = code;
    for (int p = 0; p < 4; p++) {
        tp.wcw[p] = (const float*)d_in[7 + 4 * p];
        tp.wcb[p] = (const float*)d_in[8 + 4 * p];
        tp.lng[p] = (const float*)d_in[9 + 4 * p];
        tp.lnb[p] = (const float*)d_in[10 + 4 * p];
    }

    cudaFuncSetAttribute(attn_mma_kernel, cudaFuncAttributeMaxDynamicSharedMemorySize,
                         AT_SMEM_BYTES);

    // 1) transformed codes
    tc_kernel<<<4, 256>>>(tp);
    // 2) split-bf16 conversions (tc folded into A operands)
    conv_in_kernel<<<dim3(BB * SS * DD / 4 / 256, 3), 256>>>(query, key, value);
    conv_w_kernel<<<DD * DD / 4 / 256, 256>>>(W);
    // 3) Q/K/V projections on HMMA
    gemm_mma_kernel<<<dim3(DD / 128, BB * SS / 128, 3), 256>>>(bias, nullptr, 0);
    // 4) colsum of V
    vsum_kernel<<<BB * HH, 512>>>();
    // 5) fused attention -> attention region of d_out (streaming) + g_x
    float* att = (float*)d_out + (size_t)BB * SS * DD;
    attn_mma_kernel<<<dim3(SS / 64, HH, BB), 256, AT_SMEM_BYTES>>>(u, att);
    // 6) split-convert x, then output projection on HMMA -> x region of d_out
    conv_x_kernel<<<BB * SS * DD / 4 / 256, 256>>>();
    gemm_mma_kernel<<<dim3(DD / 128, BB * SS / 128, 1), 256>>>(bias, (float*)d_out, 3);
}

// round 9
// speedup vs baseline: 4.7218x; 1.0777x over previous
#include <cuda_runtime.h>
#include <cuda_bf16.h>
#include <math.h>
#include <cstdint>

#define BB 8
#define SS 1024
#define DD 1024
#define HH 16
#define HDD 64
#define CDD 512
#define LN_EPS 1e-5f

typedef unsigned short ushort_t;
typedef unsigned int u32;

// ---------------- scratch (device globals; no allocations) ----------------
__device__ float    g_tc[4][DD];                    // 16 KB
__device__ float    g_v32[BB * SS * DD];            // 32 MB  (projected V, f32, for colsum)
__device__ float    g_x[BB * SS * DD];              // 32 MB  (attention out, pre O-proj)
__device__ ushort_t g_hi[4][BB * SS * DD];          // 64 MB  (split-bf16 hi of GEMM A operands)
__device__ ushort_t g_lo[4][BB * SS * DD];          // 64 MB
__device__ ushort_t g_whi[DD * DD];                 // 2 MB
__device__ ushort_t g_wlo[DD * DD];                 // 2 MB
__device__ ushort_t g_qkvh[3][BB * SS * DD];        // 48 MB  (projected Q,K,V bf16)
__device__ float    g_vsum[BB * HH * HDD];          // 32 KB  (colsum of V per (b,h))

// ---------------- helpers ----------------
__device__ __forceinline__ void mma_bf16(float4& d, const u32 a[4], u32 b0, u32 b1) {
    asm volatile("mma.sync.aligned.m16n8k16.row.col.f32.bf16.bf16.f32 "
                 "{%0,%1,%2,%3}, {%4,%5,%6,%7}, {%8,%9}, {%0,%1,%2,%3};"
                 : "+f"(d.x), "+f"(d.y), "+f"(d.z), "+f"(d.w)
                 : "r"(a[0]), "r"(a[1]), "r"(a[2]), "r"(a[3]), "r"(b0), "r"(b1));
}
__device__ __forceinline__ void stcs2(float* p, float a, float b) {
    asm volatile("st.global.cs.v2.f32 [%0], {%1,%2};" :: "l"(p), "f"(a), "f"(b));
}
__device__ __forceinline__ u32 pack_bf16x2(float a, float b) {
    return (u32)__bfloat16_as_ushort(__float2bfloat16(a))
         | ((u32)__bfloat16_as_ushort(__float2bfloat16(b)) << 16);
}
__device__ __forceinline__ void cp16(ushort_t* s, const ushort_t* g) {
    u32 sa = (u32)__cvta_generic_to_shared(s);
    asm volatile("cp.async.cg.shared.global [%0], [%1], 16;" :: "r"(sa), "l"(g));
}
#define CP_COMMIT() asm volatile("cp.async.commit_group;" ::: "memory")
#define CP_WAIT(n)  asm volatile("cp.async.wait_group %0;" :: "n"(n) : "memory")

// ---------------- kernel 1: tc_p = LayerNorm(code @ wc_w^T + wc_b) ----------------
struct TcParams {
    const float* code;
    const float* wcw[4];
    const float* wcb[4];
    const float* lng[4];
    const float* lnb[4];
};

__global__ __launch_bounds__(256) void tc_kernel(TcParams P) {
    int p = blockIdx.x, t = threadIdx.x;
    __shared__ float sc[CDD];
    __shared__ float raw[DD];
    __shared__ float red[256];
    for (int i = t; i < CDD; i += 256) sc[i] = P.code[i];
    __syncthreads();
    const float* w  = P.wcw[p];
    const float* wb = P.wcb[p];
    for (int k = 0; k < 4; k++) {
        int d = t + k * 256;
        const float4* wr = (const float4*)(w + (size_t)d * CDD);
        const float4* s4 = (const float4*)sc;
        float s = wb[d];
        #pragma unroll 8
        for (int c = 0; c < CDD / 4; c++) {
            float4 wv = wr[c];
            float4 cv = s4[c];
            s += wv.x * cv.x + wv.y * cv.y + wv.z * cv.z + wv.w * cv.w;
        }
        raw[d] = s;
    }
    __syncthreads();
    float ls = 0.f, lq = 0.f;
    for (int k = 0; k < 4; k++) {
        float v = raw[t + k * 256];
        ls += v; lq += v * v;
    }
    red[t] = ls; __syncthreads();
    for (int o = 128; o > 0; o >>= 1) { if (t < o) red[t] += red[t + o]; __syncthreads(); }
    float sum = red[0]; __syncthreads();
    red[t] = lq; __syncthreads();
    for (int o = 128; o > 0; o >>= 1) { if (t < o) red[t] += red[t + o]; __syncthreads(); }
    float sq  = red[0];
    float mu  = sum * (1.f / DD);
    float var = sq * (1.f / DD) - mu * mu;
    float inv = rsqrtf(var + LN_EPS);
    const float* g  = P.lng[p];
    const float* be = P.lnb[p];
    for (int k = 0; k < 4; k++) {
        int d = t + k * 256;
        g_tc[p][d] = (raw[d] - mu) * inv * g[d] + be[d];
    }
}

// ---------------- conversions: fp32 (x tc) -> split bf16 (hi, lo) ----------------
__device__ __forceinline__ void split_store(float4 a, ushort_t* hi, ushort_t* lo, size_t i4) {
    unsigned hx = __bfloat16_as_ushort(__float2bfloat16(a.x));
    unsigned hy = __bfloat16_as_ushort(__float2bfloat16(a.y));
    unsigned hz = __bfloat16_as_ushort(__float2bfloat16(a.z));
    unsigned hw = __bfloat16_as_ushort(__float2bfloat16(a.w));
    float rx = a.x - __bfloat162float(__ushort_as_bfloat16((ushort_t)hx));
    float ry = a.y - __bfloat162float(__ushort_as_bfloat16((ushort_t)hy));
    float rz = a.z - __bfloat162float(__ushort_as_bfloat16((ushort_t)hz));
    float rw = a.w - __bfloat162float(__ushort_as_bfloat16((ushort_t)hw));
    unsigned lx = __bfloat16_as_ushort(__float2bfloat16(rx));
    unsigned ly = __bfloat16_as_ushort(__float2bfloat16(ry));
    unsigned lz = __bfloat16_as_ushort(__float2bfloat16(rz));
    unsigned lw = __bfloat16_as_ushort(__float2bfloat16(rw));
    ((uint2*)hi)[i4] = make_uint2(hx | (hy << 16), hz | (hw << 16));
    ((uint2*)lo)[i4] = make_uint2(lx | (ly << 16), lz | (lw << 16));
}

__global__ __launch_bounds__(256) void conv_in_kernel(const float* __restrict__ q,
                                                      const float* __restrict__ k,
                                                      const float* __restrict__ v) {
    int z = blockIdx.y;
    const float* in = (z == 0) ? q : (z == 1) ? k : v;
    size_t i4 = (size_t)blockIdx.x * 256 + threadIdx.x;
    float4 a = ((const float4*)in)[i4];
    int kc = (int)((i4 * 4) & (DD - 1));
    float4 t = *(const float4*)&g_tc[z][kc];
    a.x *= t.x; a.y *= t.y; a.z *= t.z; a.w *= t.w;
    split_store(a, g_hi[z], g_lo[z], i4);
}

__global__ __launch_bounds__(256) void conv_x_kernel() {
    size_t i4 = (size_t)blockIdx.x * 256 + threadIdx.x;
    float4 a = ((const float4*)g_x)[i4];
    int kc = (int)((i4 * 4) & (DD - 1));
    float4 t = *(const float4*)&g_tc[3][kc];
    a.x *= t.x; a.y *= t.y; a.z *= t.z; a.w *= t.w;
    split_store(a, g_hi[3], g_lo[3], i4);
}

__global__ __launch_bounds__(256) void conv_w_kernel(const float* __restrict__ W) {
    size_t i4 = (size_t)blockIdx.x * 256 + threadIdx.x;
    float4 a = ((const float4*)W)[i4];
    split_store(a, g_whi, g_wlo, i4);
}

// ---------------- vsum: colsum of projected V per (b,h) ----------------
__global__ __launch_bounds__(512) void vsum_kernel() {
    int bh = blockIdx.x;
    int b = bh >> 4, h = bh & 15;
    int tid = threadIdx.x;
    int d = tid & 63, jg = tid >> 6;
    const float* Vp = g_v32 + (size_t)b * SS * DD + h * HDD + d;
    float s = 0.f;
    for (int j = jg * 128; j < jg * 128 + 128; j++) s += Vp[(size_t)j * DD];
    __shared__ float rs[512];
    rs[tid] = s;
    __syncthreads();
    if (tid < 64) {
        float t = 0.f;
        #pragma unroll
        for (int k = 0; k < 8; k++) t += rs[k * 64 + tid];
        g_vsum[bh * 64 + tid] = t;
    }
}

// ---------------- projection GEMM on HMMA, cp.async double-buffered -------------
// C[r,n] = sum_k A[r,k]*W[n,k] + b[n]; split-bf16 3-term; block 128x128, 8 warps.
#define PST 40
#define GST (128 * PST)                    // ushorts per stage per array
#define GEMM_SMEM (4 * 2 * GST * 2 + 512)  // 82432 B

__global__ __launch_bounds__(256, 2) void gemm_mma_kernel(const float* __restrict__ bias,
                                                          float* __restrict__ cout, int zbase) {
    extern __shared__ __align__(16) ushort_t gsm[];
    ushort_t* Ah = gsm;                 // [2][GST]
    ushort_t* Al = Ah + 2 * GST;
    ushort_t* Bh = Al + 2 * GST;
    ushort_t* Bl = Bh + 2 * GST;
    float* sbias = (float*)(Bl + 2 * GST);

    int z = blockIdx.z + zbase;
    const ushort_t* Ahg = g_hi[z];
    const ushort_t* Alg = g_lo[z];
    float*    Cf = (z == 2) ? g_v32 : ((z == 3) ? cout : nullptr);
    ushort_t* Cb = (z < 3) ? g_qkvh[z] : nullptr;

    int tid = threadIdx.x;
    int wid = tid >> 5, lane = tid & 31;
    int g = lane >> 2, tig = lane & 3;
    int wr = wid & 1, wc = wid >> 1;
    int bm = blockIdx.y * 128, bn = blockIdx.x * 128;

    // per-thread load coords (2 segments of the chunk)
    int r0l = tid >> 2, c8l = (tid & 3) * 8;          // rows 0..63
    int r1l = r0l + 64;

    float4 acc[4][4];
    #pragma unroll
    for (int i = 0; i < 4; i++)
        #pragma unroll
        for (int j = 0; j < 4; j++) acc[i][j] = make_float4(0.f, 0.f, 0.f, 0.f);

    if (tid < 128) sbias[tid] = bias[bn + tid];

    // prologue: chunk 0 -> stage 0
    {
        size_t gA0 = (size_t)(bm + r0l) * DD + c8l, gA1 = (size_t)(bm + r1l) * DD + c8l;
        size_t gB0 = (size_t)(bn + r0l) * DD + c8l, gB1 = (size_t)(bn + r1l) * DD + c8l;
        cp16(&Ah[r0l * PST + c8l], &Ahg[gA0]); cp16(&Ah[r1l * PST + c8l], &Ahg[gA1]);
        cp16(&Al[r0l * PST + c8l], &Alg[gA0]); cp16(&Al[r1l * PST + c8l], &Alg[gA1]);
        cp16(&Bh[r0l * PST + c8l], &g_whi[gB0]); cp16(&Bh[r1l * PST + c8l], &g_whi[gB1]);
        cp16(&Bl[r0l * PST + c8l], &g_wlo[gB0]); cp16(&Bl[r1l * PST + c8l], &g_wlo[gB1]);
        CP_COMMIT();
    }

    #pragma unroll 1
    for (int kc = 0; kc < DD / 32; kc++) {
        if (kc + 1 < DD / 32) {
            int st = ((kc + 1) & 1) * GST;
            int ko = (kc + 1) * 32;
            size_t gA0 = (size_t)(bm + r0l) * DD + ko + c8l, gA1 = (size_t)(bm + r1l) * DD + ko + c8l;
            size_t gB0 = (size_t)(bn + r0l) * DD + ko + c8l, gB1 = (size_t)(bn + r1l) * DD + ko + c8l;
            cp16(&Ah[st + r0l * PST + c8l], &Ahg[gA0]); cp16(&Ah[st + r1l * PST + c8l], &Ahg[gA1]);
            cp16(&Al[st + r0l * PST + c8l], &Alg[gA0]); cp16(&Al[st + r1l * PST + c8l], &Alg[gA1]);
            cp16(&Bh[st + r0l * PST + c8l], &g_whi[gB0]); cp16(&Bh[st + r1l * PST + c8l], &g_whi[gB1]);
            cp16(&Bl[st + r0l * PST + c8l], &g_wlo[gB0]); cp16(&Bl[st + r1l * PST + c8l], &g_wlo[gB1]);
            CP_COMMIT();
            CP_WAIT(1);
        } else {
            CP_WAIT(0);
        }
        __syncthreads();

        int cur = (kc & 1) * GST;
        const ushort_t* Ahc = Ah + cur;
        const ushort_t* Alc = Al + cur;
        const ushort_t* Bhc = Bh + cur;
        const ushort_t* Blc = Bl + cur;
        #pragma unroll
        for (int ks = 0; ks < 2; ks++) {
            int k0 = ks * 16;
            u32 ah[4][4], al[4][4];
            #pragma unroll
            for (int mf = 0; mf < 4; mf++) {
                int r0 = wr * 64 + mf * 16 + g;
                const ushort_t* p0 = Ahc + r0 * PST + k0 + 2 * tig;
                const ushort_t* p1 = p0 + 8 * PST;
                ah[mf][0] = *(const u32*)p0;       ah[mf][1] = *(const u32*)p1;
                ah[mf][2] = *(const u32*)(p0 + 8); ah[mf][3] = *(const u32*)(p1 + 8);
                const ushort_t* q0 = Alc + r0 * PST + k0 + 2 * tig;
                const ushort_t* q1 = q0 + 8 * PST;
                al[mf][0] = *(const u32*)q0;       al[mf][1] = *(const u32*)q1;
                al[mf][2] = *(const u32*)(q0 + 8); al[mf][3] = *(const u32*)(q1 + 8);
            }
            #pragma unroll
            for (int nf = 0; nf < 4; nf++) {
                int n0 = wc * 32 + nf * 8 + g;
                const ushort_t* bp = Bhc + n0 * PST + k0 + 2 * tig;
                u32 bh0 = *(const u32*)bp, bh1 = *(const u32*)(bp + 8);
                const ushort_t* lp = Blc + n0 * PST + k0 + 2 * tig;
                u32 bl0 = *(const u32*)lp, bl1 = *(const u32*)(lp + 8);
                #pragma unroll
                for (int mf = 0; mf < 4; mf++) {
                    mma_bf16(acc[mf][nf], ah[mf], bh0, bh1);
                    mma_bf16(acc[mf][nf], ah[mf], bl0, bl1);
                    mma_bf16(acc[mf][nf], al[mf], bh0, bh1);
                }
            }
        }
        __syncthreads();
    }

    // epilogue
    #pragma unroll
    for (int mf = 0; mf < 4; mf++) {
        int r0 = bm + wr * 64 + mf * 16 + g;
        #pragma unroll
        for (int nf = 0; nf < 4; nf++) {
            int cl = wc * 32 + nf * 8 + 2 * tig;
            int c  = bn + cl;
            float2 b2 = *(const float2*)&sbias[cl];
            float4 v = acc[mf][nf];
            float o0x = v.x + b2.x, o0y = v.y + b2.y;
            float o1x = v.z + b2.x, o1y = v.w + b2.y;
            if (Cf) {
                *(float2*)&Cf[(size_t)r0 * DD + c]       = make_float2(o0x, o0y);
                *(float2*)&Cf[(size_t)(r0 + 8) * DD + c] = make_float2(o1x, o1y);
            }
            if (Cb) {
                *(u32*)&Cb[(size_t)r0 * DD + c]       = pack_bf16x2(o0x, o0y);
                *(u32*)&Cb[(size_t)(r0 + 8) * DD + c] = pack_bf16x2(o1x, o1y);
            }
        }
    }
}

// ---------------- fused attention on HMMA, double-buffered ----------------
#define QS2 72
#define KS2 72
#define VS2 132
#define GS2 132
#define AT_Q  0
#define AT_K  (AT_Q + 64 * QS2)               // 2 stages of [128][KS2]
#define AT_V  (AT_K + 2 * 128 * KS2)          // 2 stages of [64][VS2]
#define AT_G  (AT_V + 2 * 64 * VS2)
#define AT_USH (AT_G + 64 * GS2)
#define AT_SMEM_BYTES (AT_USH * 2 + (SS + 64 + 128) * 4)   // 101,632 B

__global__ __launch_bounds__(256, 2) void attn_mma_kernel(const float* __restrict__ u,
                                                          float* __restrict__ att) {
    extern __shared__ __align__(16) char smemc[];
    ushort_t* Qs  = (ushort_t*)smemc + AT_Q;
    ushort_t* Ks  = (ushort_t*)smemc + AT_K;
    ushort_t* Vsh = (ushort_t*)smemc + AT_V;
    ushort_t* Gs  = (ushort_t*)smemc + AT_G;
    float* usj  = (float*)(smemc + AT_USH * 2);
    float* crow = usj + SS;
    float* red  = crow + 64;

    int tid = threadIdx.x;
    int wid = tid >> 5, lane = tid & 31;
    int g = lane >> 2, tig = lane & 3;
    int wr = wid & 3, wc = wid >> 2;
    int i0 = blockIdx.x * 64;
    int h  = blockIdx.y;
    int b  = blockIdx.z;
    const ushort_t* Qg = g_qkvh[0] + (size_t)b * SS * DD + h * HDD;
    const ushort_t* Kg = g_qkvh[1] + (size_t)b * SS * DD + h * HDD;
    const ushort_t* Vg = g_qkvh[2] + (size_t)b * SS * DD + h * HDD;

    int krow = tid >> 1, kc8 = (tid & 1) * 8;   // K cp.async coords: 128 rows x 16 ushorts? no:
    // K chunk = 128 rows x 64 ushorts = 1024 x 16B; per thread 4 segments
    // use: i = tid + t*256; row = i>>3; c8 = (i&7)*8
    (void)krow; (void)kc8;

    // load Q tile + u
    #pragma unroll
    for (int t = 0; t < 2; t++) {
        int i = tid + t * 256;
        int row = i >> 3, c8 = (i & 7) * 8;
        *(uint4*)&Qs[row * QS2 + c8] = *(const uint4*)&Qg[(size_t)(i0 + row) * DD + c8];
    }
    for (int i = tid; i < SS; i += 256) usj[i] = u[b * SS + i];

    // ---- pass 1: rowsums of exp(E/8), K double-buffered via cp.async ----
    {
        #pragma unroll
        for (int t = 0; t < 4; t++) {
            int i = tid + t * 256;
            int row = i >> 3, c8 = (i & 7) * 8;
            cp16(&Ks[row * KS2 + c8], &Kg[(size_t)row * DD + c8]);
        }
        CP_COMMIT();
    }
    float s0 = 0.f, s1 = 0.f;
    #pragma unroll 1
    for (int jt = 0; jt < 8; jt++) {
        if (jt + 1 < 8) {
            int st = ((jt + 1) & 1) * 128 * KS2;
            int j0n = (jt + 1) * 128;
            #pragma unroll
            for (int t = 0; t < 4; t++) {
                int i = tid + t * 256;
                int row = i >> 3, c8 = (i & 7) * 8;
                cp16(&Ks[st + row * KS2 + c8], &Kg[(size_t)(j0n + row) * DD + c8]);
            }
            CP_COMMIT();
            CP_WAIT(1);
        } else {
            CP_WAIT(0);
        }
        __syncthreads();
        const ushort_t* Kb = Ks + (jt & 1) * 128 * KS2;
        float4 eacc[8];
        #pragma unroll
        for (int nf = 0; nf < 8; nf++) eacc[nf] = make_float4(0.f, 0.f, 0.f, 0.f);
        #pragma unroll
        for (int ks = 0; ks < 4; ks++) {
            int k0 = ks * 16;
            u32 a[4];
            const ushort_t* p0 = Qs + (16 * wr + g) * QS2 + k0 + 2 * tig;
            const ushort_t* p1 = p0 + 8 * QS2;
            a[0] = *(const u32*)p0;       a[1] = *(const u32*)p1;
            a[2] = *(const u32*)(p0 + 8); a[3] = *(const u32*)(p1 + 8);
            #pragma unroll
            for (int nf = 0; nf < 8; nf++) {
                const ushort_t* q0 = Kb + (64 * wc + nf * 8 + g) * KS2 + k0 + 2 * tig;
                mma_bf16(eacc[nf], a, *(const u32*)q0, *(const u32*)(q0 + 8));
            }
        }
        #pragma unroll
        for (int nf = 0; nf < 8; nf++) {
            float4 e = eacc[nf];
            s0 += __expf(e.x * 0.125f) + __expf(e.y * 0.125f);
            s1 += __expf(e.z * 0.125f) + __expf(e.w * 0.125f);
        }
        __syncthreads();
    }
    s0 += __shfl_xor_sync(0xffffffffu, s0, 1);
    s0 += __shfl_xor_sync(0xffffffffu, s0, 2);
    s1 += __shfl_xor_sync(0xffffffffu, s1, 1);
    s1 += __shfl_xor_sync(0xffffffffu, s1, 2);
    if (tig == 0) {
        red[wc * 64 + 16 * wr + g]     = s0;
        red[wc * 64 + 16 * wr + g + 8] = s1;
    }
    __syncthreads();
    if (tid < 64) crow[tid] = 1e-6f * (red[tid] + red[64 + tid]) / usj[i0 + tid];

    // ---- pass 2: K cp.async double-buffer, V register-prefetch double-buffer ----
    int wr2 = wid & 3, wc2 = wid >> 2;
    float4 xacc[4];
    #pragma unroll
    for (int nf = 0; nf < 4; nf++) xacc[nf] = make_float4(0.f, 0.f, 0.f, 0.f);

    u32 vreg[16];
    {
        // prologue: K chunk 0 cp.async, V chunk 0 LDG
        #pragma unroll
        for (int t = 0; t < 4; t++) {
            int i = tid + t * 256;
            int row = i >> 3, c8 = (i & 7) * 8;
            cp16(&Ks[row * KS2 + c8], &Kg[(size_t)row * DD + c8]);
        }
        CP_COMMIT();
        #pragma unroll
        for (int t = 0; t < 16; t++) {
            int i = tid + t * 256;
            int dp = i & 31, j = i >> 5;
            vreg[t] = *(const u32*)&Vg[(size_t)j * DD + 2 * dp];
        }
    }

    #pragma unroll 1
    for (int jt = 0; jt < 8; jt++) {
        int j0 = jt * 128;
        // issue next K
        if (jt + 1 < 8) {
            int st = ((jt + 1) & 1) * 128 * KS2;
            int j0n = (jt + 1) * 128;
            #pragma unroll
            for (int t = 0; t < 4; t++) {
                int i = tid + t * 256;
                int row = i >> 3, c8 = (i & 7) * 8;
                cp16(&Ks[st + row * KS2 + c8], &Kg[(size_t)(j0n + row) * DD + c8]);
            }
            CP_COMMIT();
        }
        // STS current V (transposed)
        {
            ushort_t* Vb = Vsh + (jt & 1) * 64 * VS2;
            #pragma unroll
            for (int t = 0; t < 16; t++) {
                int i = tid + t * 256;
                int dp = i & 31, j = i >> 5;
                u32 vh = vreg[t];
                Vb[(2 * dp) * VS2 + j]     = (ushort_t)(vh & 0xffffu);
                Vb[(2 * dp + 1) * VS2 + j] = (ushort_t)(vh >> 16);
            }
        }
        // LDG next V
        if (jt + 1 < 8) {
            int j0n = (jt + 1) * 128;
            #pragma unroll
            for (int t = 0; t < 16; t++) {
                int i = tid + t * 256;
                int dp = i & 31, j = i >> 5;
                vreg[t] = *(const u32*)&Vg[(size_t)(j0n + j) * DD + 2 * dp];
            }
        }
        if (jt + 1 < 8) { CP_WAIT(1); } else { CP_WAIT(0); }
        __syncthreads();

        const ushort_t* Kb = Ks + (jt & 1) * 128 * KS2;
        const ushort_t* Vb = Vsh + (jt & 1) * 64 * VS2;

        // QK
        float4 eacc[8];
        #pragma unroll
        for (int nf = 0; nf < 8; nf++) eacc[nf] = make_float4(0.f, 0.f, 0.f, 0.f);
        #pragma unroll
        for (int ks = 0; ks < 4; ks++) {
            int k0 = ks * 16;
            u32 a[4];
            const ushort_t* p0 = Qs + (16 * wr + g) * QS2 + k0 + 2 * tig;
            const ushort_t* p1 = p0 + 8 * QS2;
            a[0] = *(const u32*)p0;       a[1] = *(const u32*)p1;
            a[2] = *(const u32*)(p0 + 8); a[3] = *(const u32*)(p1 + 8);
            #pragma unroll
            for (int nf = 0; nf < 8; nf++) {
                const ushort_t* q0 = Kb + (64 * wc + nf * 8 + g) * KS2 + k0 + 2 * tig;
                mma_bf16(eacc[nf], a, *(const u32*)q0, *(const u32*)(q0 + 8));
            }
        }
        // f + streaming store + G
        int ra = 16 * wr + g, rb = ra + 8;
        float ca = crow[ra], cb = crow[rb];
        float* atta = att + (((size_t)(b * HH + h)) * SS + (i0 + ra)) * SS + j0;
        float* attb = att + (((size_t)(b * HH + h)) * SS + (i0 + rb)) * SS + j0;
        #pragma unroll
        for (int nf = 0; nf < 8; nf++) {
            int col = 64 * wc + 8 * nf + 2 * tig;
            float2 uj = *(const float2*)&usj[j0 + col];
            float4 e = eacc[nf];
            float t0 = uj.x * __expf(e.x * 0.125f);
            float t1 = uj.y * __expf(e.y * 0.125f);
            float t2 = uj.x * __expf(e.z * 0.125f);
            float t3 = uj.y * __expf(e.w * 0.125f);
            float f0 = __fdividef(t0, ca + t0);
            float f1 = __fdividef(t1, ca + t1);
            float f2 = __fdividef(t2, cb + t2);
            float f3 = __fdividef(t3, cb + t3);
            stcs2(atta + col, f0, f1);
            stcs2(attb + col, f2, f3);
            *(u32*)&Gs[ra * GS2 + col] = pack_bf16x2(1.f - f0, 1.f - f1);
            *(u32*)&Gs[rb * GS2 + col] = pack_bf16x2(1.f - f2, 1.f - f3);
        }
        __syncthreads();
        // GV accumulate
        #pragma unroll
        for (int ks = 0; ks < 8; ks++) {
            int k0 = ks * 16;
            u32 a[4];
            const ushort_t* p0 = Gs + (16 * wr2 + g) * GS2 + k0 + 2 * tig;
            const ushort_t* p1 = p0 + 8 * GS2;
            a[0] = *(const u32*)p0;       a[1] = *(const u32*)p1;
            a[2] = *(const u32*)(p0 + 8); a[3] = *(const u32*)(p1 + 8);
            #pragma unroll
            for (int nf = 0; nf < 4; nf++) {
                const ushort_t* q0 = Vb + (32 * wc2 + nf * 8 + g) * VS2 + k0 + 2 * tig;
                mma_bf16(xacc[nf], a, *(const u32*)q0, *(const u32*)(q0 + 8));
            }
        }
    }

    // epilogue: x = colsum(V) - G@V
    {
        const float* vs = g_vsum + (b * HH + h) * HDD;
        int ra = 16 * wr2 + g, rb = ra + 8;
        #pragma unroll
        for (int nf = 0; nf < 4; nf++) {
            int col = 32 * wc2 + 8 * nf + 2 * tig;
            float2 v2 = *(const float2*)&vs[col];
            float4 xv = xacc[nf];
            float* xa = g_x + ((size_t)b * SS + i0 + ra) * DD + h * HDD + col;
            float* xb = g_x + ((size_t)b * SS + i0 + rb) * DD + h * HDD + col;
            *(float2*)xa = make_float2(v2.x - xv.x, v2.y - xv.y);
            *(float2*)xb = make_float2(v2.x - xv.z, v2.y - xv.w);
        }
    }
}

// ---------------- launch ----------------
extern "C" void kernel_launch(void* const* d_in, const int* in_sizes, int n_in,
                              void* d_out, int out_size) {
    const float* query = (const float*)d_in[0];
    const float* key   = (const float*)d_in[1];
    const float* value = (const float*)d_in[2];
    const float* u     = (const float*)d_in[3];
    const float* code  = (const float*)d_in[4];
    const float* W     = (const float*)d_in[5];
    const float* bias  = (const float*)d_in[6];

    TcParams tp;
    tp.code = code;
    for (int p = 0; p < 4; p++) {
        tp.wcw[p] = (const float*)d_in[7 + 4 * p];
        tp.wcb[p] = (const float*)d_in[8 + 4 * p];
        tp.lng[p] = (const float*)d_in[9 + 4 * p];
        tp.lnb[p] = (const float*)d_in[10 + 4 * p];
    }

    cudaFuncSetAttribute(gemm_mma_kernel, cudaFuncAttributeMaxDynamicSharedMemorySize,
                         GEMM_SMEM);
    cudaFuncSetAttribute(attn_mma_kernel, cudaFuncAttributeMaxDynamicSharedMemorySize,
                         AT_SMEM_BYTES);

    // 1) transformed codes
    tc_kernel<<<4, 256>>>(tp);
    // 2) split-bf16 conversions (tc folded into A operands)
    conv_in_kernel<<<dim3(BB * SS * DD / 4 / 256, 3), 256>>>(query, key, value);
    conv_w_kernel<<<DD * DD / 4 / 256, 256>>>(W);
    // 3) Q/K/V projections on HMMA (double-buffered)
    gemm_mma_kernel<<<dim3(DD / 128, BB * SS / 128, 3), 256, GEMM_SMEM>>>(bias, nullptr, 0);
    // 4) colsum of V
    vsum_kernel<<<BB * HH, 512>>>();
    // 5) fused attention -> attention region of d_out (streaming) + g_x
    float* att = (float*)d_out + (size_t)BB * SS * DD;
    attn_mma_kernel<<<dim3(SS / 64, HH, BB), 256, AT_SMEM_BYTES>>>(u, att);
    // 6) split-convert x, then output projection on HMMA -> x region of d_out
    conv_x_kernel<<<BB * SS * DD / 4 / 256, 256>>>();
    gemm_mma_kernel<<<dim3(DD / 128, BB * SS / 128, 1), 256, GEMM_SMEM>>>(bias, (float*)d_out, 3);
}

// round 10
// speedup vs baseline: 5.2562x; 1.1132x over previous
#include <cuda_runtime.h>
#include <cuda_bf16.h>
#include <math.h>
#include <cstdint>

#define BB 8
#define SS 1024
#define DD 1024
#define HH 16
#define HDD 64
#define CDD 512
#define LN_EPS 1e-5f

typedef unsigned short ushort_t;
typedef unsigned int u32;

// ---------------- scratch (device globals; no allocations) ----------------
__device__ float    g_tc[4][DD];                    // 16 KB
__device__ float    g_v32[BB * SS * DD];            // 32 MB  (projected V, f32, for colsum)
__device__ float    g_x[BB * SS * DD];              // 32 MB  (attention out, pre O-proj)
__device__ ushort_t g_hi[4][BB * SS * DD];          // 64 MB  (split-bf16 hi of GEMM A operands)
__device__ ushort_t g_lo[4][BB * SS * DD];          // 64 MB  (lo used only for V and x)
__device__ ushort_t g_whi[DD * DD];                 // 2 MB
__device__ ushort_t g_wlo[DD * DD];                 // 2 MB
__device__ ushort_t g_qkvh[3][BB * SS * DD];        // 48 MB  (projected Q,K,V bf16)
__device__ float    g_vsum[BB * HH * HDD];          // 32 KB  (colsum of V per (b,h))

// ---------------- helpers ----------------
__device__ __forceinline__ void mma_bf16(float4& d, const u32 a[4], u32 b0, u32 b1) {
    asm volatile("mma.sync.aligned.m16n8k16.row.col.f32.bf16.bf16.f32 "
                 "{%0,%1,%2,%3}, {%4,%5,%6,%7}, {%8,%9}, {%0,%1,%2,%3};"
                 : "+f"(d.x), "+f"(d.y), "+f"(d.z), "+f"(d.w)
                 : "r"(a[0]), "r"(a[1]), "r"(a[2]), "r"(a[3]), "r"(b0), "r"(b1));
}
__device__ __forceinline__ void stcs2(float* p, float a, float b) {
    asm volatile("st.global.cs.v2.f32 [%0], {%1,%2};" :: "l"(p), "f"(a), "f"(b));
}
__device__ __forceinline__ u32 pack_bf16x2(float a, float b) {
    return (u32)__bfloat16_as_ushort(__float2bfloat16(a))
         | ((u32)__bfloat16_as_ushort(__float2bfloat16(b)) << 16);
}
__device__ __forceinline__ void cp16(ushort_t* s, const ushort_t* g) {
    u32 sa = (u32)__cvta_generic_to_shared(s);
    asm volatile("cp.async.cg.shared.global [%0], [%1], 16;" :: "r"(sa), "l"(g));
}
#define CP_COMMIT() asm volatile("cp.async.commit_group;" ::: "memory")
#define CP_WAIT(n)  asm volatile("cp.async.wait_group %0;" :: "n"(n) : "memory")

// ---------------- kernel 1: tc_p = LayerNorm(code @ wc_w^T + wc_b) ----------------
struct TcParams {
    const float* code;
    const float* wcw[4];
    const float* wcb[4];
    const float* lng[4];
    const float* lnb[4];
};

__global__ __launch_bounds__(256) void tc_kernel(TcParams P) {
    int p = blockIdx.x, t = threadIdx.x;
    __shared__ float sc[CDD];
    __shared__ float raw[DD];
    __shared__ float red[256];
    for (int i = t; i < CDD; i += 256) sc[i] = P.code[i];
    __syncthreads();
    const float* w  = P.wcw[p];
    const float* wb = P.wcb[p];
    for (int k = 0; k < 4; k++) {
        int d = t + k * 256;
        const float4* wr = (const float4*)(w + (size_t)d * CDD);
        const float4* s4 = (const float4*)sc;
        float s = wb[d];
        #pragma unroll 8
        for (int c = 0; c < CDD / 4; c++) {
            float4 wv = wr[c];
            float4 cv = s4[c];
            s += wv.x * cv.x + wv.y * cv.y + wv.z * cv.z + wv.w * cv.w;
        }
        raw[d] = s;
    }
    __syncthreads();
    float ls = 0.f, lq = 0.f;
    for (int k = 0; k < 4; k++) {
        float v = raw[t + k * 256];
        ls += v; lq += v * v;
    }
    red[t] = ls; __syncthreads();
    for (int o = 128; o > 0; o >>= 1) { if (t < o) red[t] += red[t + o]; __syncthreads(); }
    float sum = red[0]; __syncthreads();
    red[t] = lq; __syncthreads();
    for (int o = 128; o > 0; o >>= 1) { if (t < o) red[t] += red[t + o]; __syncthreads(); }
    float sq  = red[0];
    float mu  = sum * (1.f / DD);
    float var = sq * (1.f / DD) - mu * mu;
    float inv = rsqrtf(var + LN_EPS);
    const float* g  = P.lng[p];
    const float* be = P.lnb[p];
    for (int k = 0; k < 4; k++) {
        int d = t + k * 256;
        g_tc[p][d] = (raw[d] - mu) * inv * g[d] + be[d];
    }
}

// ---------------- conversions: fp32 (x tc) -> split bf16 (hi, lo) ----------------
__device__ __forceinline__ void split_store(float4 a, ushort_t* hi, ushort_t* lo,
                                            size_t i4, int want_lo) {
    unsigned hx = __bfloat16_as_ushort(__float2bfloat16(a.x));
    unsigned hy = __bfloat16_as_ushort(__float2bfloat16(a.y));
    unsigned hz = __bfloat16_as_ushort(__float2bfloat16(a.z));
    unsigned hw = __bfloat16_as_ushort(__float2bfloat16(a.w));
    ((uint2*)hi)[i4] = make_uint2(hx | (hy << 16), hz | (hw << 16));
    if (want_lo) {
        float rx = a.x - __bfloat162float(__ushort_as_bfloat16((ushort_t)hx));
        float ry = a.y - __bfloat162float(__ushort_as_bfloat16((ushort_t)hy));
        float rz = a.z - __bfloat162float(__ushort_as_bfloat16((ushort_t)hz));
        float rw = a.w - __bfloat162float(__ushort_as_bfloat16((ushort_t)hw));
        unsigned lx = __bfloat16_as_ushort(__float2bfloat16(rx));
        unsigned ly = __bfloat16_as_ushort(__float2bfloat16(ry));
        unsigned lz = __bfloat16_as_ushort(__float2bfloat16(rz));
        unsigned lw = __bfloat16_as_ushort(__float2bfloat16(rw));
        ((uint2*)lo)[i4] = make_uint2(lx | (ly << 16), lz | (lw << 16));
    }
}

__global__ __launch_bounds__(256) void conv_in_kernel(const float* __restrict__ q,
                                                      const float* __restrict__ k,
                                                      const float* __restrict__ v) {
    int z = blockIdx.y;
    const float* in = (z == 0) ? q : (z == 1) ? k : v;
    size_t i4 = (size_t)blockIdx.x * 256 + threadIdx.x;
    float4 a = ((const float4*)in)[i4];
    int kc = (int)((i4 * 4) & (DD - 1));
    float4 t = *(const float4*)&g_tc[z][kc];
    a.x *= t.x; a.y *= t.y; a.z *= t.z; a.w *= t.w;
    split_store(a, g_hi[z], g_lo[z], i4, z == 2);   // lo needed only for V
}

__global__ __launch_bounds__(256) void conv_x_kernel() {
    size_t i4 = (size_t)blockIdx.x * 256 + threadIdx.x;
    float4 a = ((const float4*)g_x)[i4];
    int kc = (int)((i4 * 4) & (DD - 1));
    float4 t = *(const float4*)&g_tc[3][kc];
    a.x *= t.x; a.y *= t.y; a.z *= t.z; a.w *= t.w;
    split_store(a, g_hi[3], g_lo[3], i4, 1);
}

__global__ __launch_bounds__(256) void conv_w_kernel(const float* __restrict__ W) {
    size_t i4 = (size_t)blockIdx.x * 256 + threadIdx.x;
    float4 a = ((const float4*)W)[i4];
    split_store(a, g_whi, g_wlo, i4, 1);
}

// ---------------- vsum: colsum of projected V per (b,h) ----------------
__global__ __launch_bounds__(512) void vsum_kernel() {
    int bh = blockIdx.x;
    int b = bh >> 4, h = bh & 15;
    int tid = threadIdx.x;
    int d = tid & 63, jg = tid >> 6;
    const float* Vp = g_v32 + (size_t)b * SS * DD + h * HDD + d;
    float s = 0.f;
    for (int j = jg * 128; j < jg * 128 + 128; j++) s += Vp[(size_t)j * DD];
    __shared__ float rs[512];
    rs[tid] = s;
    __syncthreads();
    if (tid < 64) {
        float t = 0.f;
        #pragma unroll
        for (int k = 0; k < 8; k++) t += rs[k * 64 + tid];
        g_vsum[bh * 64 + tid] = t;
    }
}

// ---------------- projection GEMM on HMMA, cp.async double-buffered -------------
// C[r,n] = sum_k A[r,k]*W[n,k] + b[n]; split-bf16 (terms = 1 or 3); 128x128, 8 warps.
// Term MMAs issued as separate mf-sweeps: same-acc reuse distance 4 (RAW hiding).
#define PST 40
#define GST (128 * PST)                    // ushorts per stage per array
#define GEMM_SMEM (4 * 2 * GST * 2 + 512)  // 82432 B

__global__ __launch_bounds__(256, 2) void gemm_mma_kernel(const float* __restrict__ bias,
                                                          float* __restrict__ cout,
                                                          int zbase, int terms) {
    extern __shared__ __align__(16) ushort_t gsm[];
    ushort_t* Ah = gsm;                 // [2][GST]
    ushort_t* Al = Ah + 2 * GST;
    ushort_t* Bh = Al + 2 * GST;
    ushort_t* Bl = Bh + 2 * GST;
    float* sbias = (float*)(Bl + 2 * GST);

    int z = blockIdx.z + zbase;
    const ushort_t* Ahg = g_hi[z];
    const ushort_t* Alg = g_lo[z];
    float*    Cf = (z == 2) ? g_v32 : ((z == 3) ? cout : nullptr);
    ushort_t* Cb = (z < 3) ? g_qkvh[z] : nullptr;

    int tid = threadIdx.x;
    int wid = tid >> 5, lane = tid & 31;
    int g = lane >> 2, tig = lane & 3;
    int wr = wid & 1, wc = wid >> 1;
    int bm = blockIdx.y * 128, bn = blockIdx.x * 128;

    int r0l = tid >> 2, c8l = (tid & 3) * 8;
    int r1l = r0l + 64;

    float4 acc[4][4];
    #pragma unroll
    for (int i = 0; i < 4; i++)
        #pragma unroll
        for (int j = 0; j < 4; j++) acc[i][j] = make_float4(0.f, 0.f, 0.f, 0.f);

    if (tid < 128) sbias[tid] = bias[bn + tid];

    // prologue: chunk 0 -> stage 0
    {
        size_t gA0 = (size_t)(bm + r0l) * DD + c8l, gA1 = (size_t)(bm + r1l) * DD + c8l;
        size_t gB0 = (size_t)(bn + r0l) * DD + c8l, gB1 = (size_t)(bn + r1l) * DD + c8l;
        cp16(&Ah[r0l * PST + c8l], &Ahg[gA0]); cp16(&Ah[r1l * PST + c8l], &Ahg[gA1]);
        cp16(&Bh[r0l * PST + c8l], &g_whi[gB0]); cp16(&Bh[r1l * PST + c8l], &g_whi[gB1]);
        if (terms == 3) {
            cp16(&Al[r0l * PST + c8l], &Alg[gA0]); cp16(&Al[r1l * PST + c8l], &Alg[gA1]);
            cp16(&Bl[r0l * PST + c8l], &g_wlo[gB0]); cp16(&Bl[r1l * PST + c8l], &g_wlo[gB1]);
        }
        CP_COMMIT();
    }

    #pragma unroll 1
    for (int kc = 0; kc < DD / 32; kc++) {
        if (kc + 1 < DD / 32) {
            int st = ((kc + 1) & 1) * GST;
            int ko = (kc + 1) * 32;
            size_t gA0 = (size_t)(bm + r0l) * DD + ko + c8l, gA1 = (size_t)(bm + r1l) * DD + ko + c8l;
            size_t gB0 = (size_t)(bn + r0l) * DD + ko + c8l, gB1 = (size_t)(bn + r1l) * DD + ko + c8l;
            cp16(&Ah[st + r0l * PST + c8l], &Ahg[gA0]); cp16(&Ah[st + r1l * PST + c8l], &Ahg[gA1]);
            cp16(&Bh[st + r0l * PST + c8l], &g_whi[gB0]); cp16(&Bh[st + r1l * PST + c8l], &g_whi[gB1]);
            if (terms == 3) {
                cp16(&Al[st + r0l * PST + c8l], &Alg[gA0]); cp16(&Al[st + r1l * PST + c8l], &Alg[gA1]);
                cp16(&Bl[st + r0l * PST + c8l], &g_wlo[gB0]); cp16(&Bl[st + r1l * PST + c8l], &g_wlo[gB1]);
            }
            CP_COMMIT();
            CP_WAIT(1);
        } else {
            CP_WAIT(0);
        }
        __syncthreads();

        int cur = (kc & 1) * GST;
        const ushort_t* Ahc = Ah + cur;
        const ushort_t* Alc = Al + cur;
        const ushort_t* Bhc = Bh + cur;
        const ushort_t* Blc = Bl + cur;
        #pragma unroll
        for (int ks = 0; ks < 2; ks++) {
            int k0 = ks * 16;
            u32 ah[4][4], al[4][4];
            #pragma unroll
            for (int mf = 0; mf < 4; mf++) {
                int r0 = wr * 64 + mf * 16 + g;
                const ushort_t* p0 = Ahc + r0 * PST + k0 + 2 * tig;
                const ushort_t* p1 = p0 + 8 * PST;
                ah[mf][0] = *(const u32*)p0;       ah[mf][1] = *(const u32*)p1;
                ah[mf][2] = *(const u32*)(p0 + 8); ah[mf][3] = *(const u32*)(p1 + 8);
            }
            if (terms == 3) {
                #pragma unroll
                for (int mf = 0; mf < 4; mf++) {
                    int r0 = wr * 64 + mf * 16 + g;
                    const ushort_t* q0 = Alc + r0 * PST + k0 + 2 * tig;
                    const ushort_t* q1 = q0 + 8 * PST;
                    al[mf][0] = *(const u32*)q0;       al[mf][1] = *(const u32*)q1;
                    al[mf][2] = *(const u32*)(q0 + 8); al[mf][3] = *(const u32*)(q1 + 8);
                }
            }
            #pragma unroll
            for (int nf = 0; nf < 4; nf++) {
                int n0 = wc * 32 + nf * 8 + g;
                const ushort_t* bp = Bhc + n0 * PST + k0 + 2 * tig;
                u32 bh0 = *(const u32*)bp, bh1 = *(const u32*)(bp + 8);
                // term 0: Ah*Bh  (mf-sweep: 4 independent accumulators)
                #pragma unroll
                for (int mf = 0; mf < 4; mf++) mma_bf16(acc[mf][nf], ah[mf], bh0, bh1);
                if (terms == 3) {
                    const ushort_t* lp = Blc + n0 * PST + k0 + 2 * tig;
                    u32 bl0 = *(const u32*)lp, bl1 = *(const u32*)(lp + 8);
                    // term 1: Ah*Bl
                    #pragma unroll
                    for (int mf = 0; mf < 4; mf++) mma_bf16(acc[mf][nf], ah[mf], bl0, bl1);
                    // term 2: Al*Bh
                    #pragma unroll
                    for (int mf = 0; mf < 4; mf++) mma_bf16(acc[mf][nf], al[mf], bh0, bh1);
                }
            }
        }
        __syncthreads();
    }

    // epilogue
    #pragma unroll
    for (int mf = 0; mf < 4; mf++) {
        int r0 = bm + wr * 64 + mf * 16 + g;
        #pragma unroll
        for (int nf = 0; nf < 4; nf++) {
            int cl = wc * 32 + nf * 8 + 2 * tig;
            int c  = bn + cl;
            float2 b2 = *(const float2*)&sbias[cl];
            float4 v = acc[mf][nf];
            float o0x = v.x + b2.x, o0y = v.y + b2.y;
            float o1x = v.z + b2.x, o1y = v.w + b2.y;
            if (Cf) {
                *(float2*)&Cf[(size_t)r0 * DD + c]       = make_float2(o0x, o0y);
                *(float2*)&Cf[(size_t)(r0 + 8) * DD + c] = make_float2(o1x, o1y);
            }
            if (Cb) {
                *(u32*)&Cb[(size_t)r0 * DD + c]       = pack_bf16x2(o0x, o0y);
                *(u32*)&Cb[(size_t)(r0 + 8) * DD + c] = pack_bf16x2(o1x, o1y);
            }
        }
    }
}

// ---------------- fused attention on HMMA, double-buffered (unchanged) ----------
#define QS2 72
#define KS2 72
#define VS2 132
#define GS2 132
#define AT_Q  0
#define AT_K  (AT_Q + 64 * QS2)
#define AT_V  (AT_K + 2 * 128 * KS2)
#define AT_G  (AT_V + 2 * 64 * VS2)
#define AT_USH (AT_G + 64 * GS2)
#define AT_SMEM_BYTES (AT_USH * 2 + (SS + 64 + 128) * 4)   // 101,632 B

__global__ __launch_bounds__(256, 2) void attn_mma_kernel(const float* __restrict__ u,
                                                          float* __restrict__ att) {
    extern __shared__ __align__(16) char smemc[];
    ushort_t* Qs  = (ushort_t*)smemc + AT_Q;
    ushort_t* Ks  = (ushort_t*)smemc + AT_K;
    ushort_t* Vsh = (ushort_t*)smemc + AT_V;
    ushort_t* Gs  = (ushort_t*)smemc + AT_G;
    float* usj  = (float*)(smemc + AT_USH * 2);
    float* crow = usj + SS;
    float* red  = crow + 64;

    int tid = threadIdx.x;
    int wid = tid >> 5, lane = tid & 31;
    int g = lane >> 2, tig = lane & 3;
    int wr = wid & 3, wc = wid >> 2;
    int i0 = blockIdx.x * 64;
    int h  = blockIdx.y;
    int b  = blockIdx.z;
    const ushort_t* Qg = g_qkvh[0] + (size_t)b * SS * DD + h * HDD;
    const ushort_t* Kg = g_qkvh[1] + (size_t)b * SS * DD + h * HDD;
    const ushort_t* Vg = g_qkvh[2] + (size_t)b * SS * DD + h * HDD;

    // load Q tile + u
    #pragma unroll
    for (int t = 0; t < 2; t++) {
        int i = tid + t * 256;
        int row = i >> 3, c8 = (i & 7) * 8;
        *(uint4*)&Qs[row * QS2 + c8] = *(const uint4*)&Qg[(size_t)(i0 + row) * DD + c8];
    }
    for (int i = tid; i < SS; i += 256) usj[i] = u[b * SS + i];

    // ---- pass 1: rowsums of exp(E/8), K double-buffered via cp.async ----
    {
        #pragma unroll
        for (int t = 0; t < 4; t++) {
            int i = tid + t * 256;
            int row = i >> 3, c8 = (i & 7) * 8;
            cp16(&Ks[row * KS2 + c8], &Kg[(size_t)row * DD + c8]);
        }
        CP_COMMIT();
    }
    float s0 = 0.f, s1 = 0.f;
    #pragma unroll 1
    for (int jt = 0; jt < 8; jt++) {
        if (jt + 1 < 8) {
            int st = ((jt + 1) & 1) * 128 * KS2;
            int j0n = (jt + 1) * 128;
            #pragma unroll
            for (int t = 0; t < 4; t++) {
                int i = tid + t * 256;
                int row = i >> 3, c8 = (i & 7) * 8;
                cp16(&Ks[st + row * KS2 + c8], &Kg[(size_t)(j0n + row) * DD + c8]);
            }
            CP_COMMIT();
            CP_WAIT(1);
        } else {
            CP_WAIT(0);
        }
        __syncthreads();
        const ushort_t* Kb = Ks + (jt & 1) * 128 * KS2;
        float4 eacc[8];
        #pragma unroll
        for (int nf = 0; nf < 8; nf++) eacc[nf] = make_float4(0.f, 0.f, 0.f, 0.f);
        #pragma unroll
        for (int ks = 0; ks < 4; ks++) {
            int k0 = ks * 16;
            u32 a[4];
            const ushort_t* p0 = Qs + (16 * wr + g) * QS2 + k0 + 2 * tig;
            const ushort_t* p1 = p0 + 8 * QS2;
            a[0] = *(const u32*)p0;       a[1] = *(const u32*)p1;
            a[2] = *(const u32*)(p0 + 8); a[3] = *(const u32*)(p1 + 8);
            #pragma unroll
            for (int nf = 0; nf < 8; nf++) {
                const ushort_t* q0 = Kb + (64 * wc + nf * 8 + g) * KS2 + k0 + 2 * tig;
                mma_bf16(eacc[nf], a, *(const u32*)q0, *(const u32*)(q0 + 8));
            }
        }
        #pragma unroll
        for (int nf = 0; nf < 8; nf++) {
            float4 e = eacc[nf];
            s0 += __expf(e.x * 0.125f) + __expf(e.y * 0.125f);
            s1 += __expf(e.z * 0.125f) + __expf(e.w * 0.125f);
        }
        __syncthreads();
    }
    s0 += __shfl_xor_sync(0xffffffffu, s0, 1);
    s0 += __shfl_xor_sync(0xffffffffu, s0, 2);
    s1 += __shfl_xor_sync(0xffffffffu, s1, 1);
    s1 += __shfl_xor_sync(0xffffffffu, s1, 2);
    if (tig == 0) {
        red[wc * 64 + 16 * wr + g]     = s0;
        red[wc * 64 + 16 * wr + g + 8] = s1;
    }
    __syncthreads();
    if (tid < 64) crow[tid] = 1e-6f * (red[tid] + red[64 + tid]) / usj[i0 + tid];

    // ---- pass 2: K cp.async double-buffer, V register-prefetch double-buffer ----
    int wr2 = wid & 3, wc2 = wid >> 2;
    float4 xacc[4];
    #pragma unroll
    for (int nf = 0; nf < 4; nf++) xacc[nf] = make_float4(0.f, 0.f, 0.f, 0.f);

    u32 vreg[16];
    {
        #pragma unroll
        for (int t = 0; t < 4; t++) {
            int i = tid + t * 256;
            int row = i >> 3, c8 = (i & 7) * 8;
            cp16(&Ks[row * KS2 + c8], &Kg[(size_t)row * DD + c8]);
        }
        CP_COMMIT();
        #pragma unroll
        for (int t = 0; t < 16; t++) {
            int i = tid + t * 256;
            int dp = i & 31, j = i >> 5;
            vreg[t] = *(const u32*)&Vg[(size_t)j * DD + 2 * dp];
        }
    }

    #pragma unroll 1
    for (int jt = 0; jt < 8; jt++) {
        int j0 = jt * 128;
        if (jt + 1 < 8) {
            int st = ((jt + 1) & 1) * 128 * KS2;
            int j0n = (jt + 1) * 128;
            #pragma unroll
            for (int t = 0; t < 4; t++) {
                int i = tid + t * 256;
                int row = i >> 3, c8 = (i & 7) * 8;
                cp16(&Ks[st + row * KS2 + c8], &Kg[(size_t)(j0n + row) * DD + c8]);
            }
            CP_COMMIT();
        }
        {
            ushort_t* Vb = Vsh + (jt & 1) * 64 * VS2;
            #pragma unroll
            for (int t = 0; t < 16; t++) {
                int i = tid + t * 256;
                int dp = i & 31, j = i >> 5;
                u32 vh = vreg[t];
                Vb[(2 * dp) * VS2 + j]     = (ushort_t)(vh & 0xffffu);
                Vb[(2 * dp + 1) * VS2 + j] = (ushort_t)(vh >> 16);
            }
        }
        if (jt + 1 < 8) {
            int j0n = (jt + 1) * 128;
            #pragma unroll
            for (int t = 0; t < 16; t++) {
                int i = tid + t * 256;
                int dp = i & 31, j = i >> 5;
                vreg[t] = *(const u32*)&Vg[(size_t)(j0n + j) * DD + 2 * dp];
            }
        }
        if (jt + 1 < 8) { CP_WAIT(1); } else { CP_WAIT(0); }
        __syncthreads();

        const ushort_t* Kb = Ks + (jt & 1) * 128 * KS2;
        const ushort_t* Vb = Vsh + (jt & 1) * 64 * VS2;

        float4 eacc[8];
        #pragma unroll
        for (int nf = 0; nf < 8; nf++) eacc[nf] = make_float4(0.f, 0.f, 0.f, 0.f);
        #pragma unroll
        for (int ks = 0; ks < 4; ks++) {
            int k0 = ks * 16;
            u32 a[4];
            const ushort_t* p0 = Qs + (16 * wr + g) * QS2 + k0 + 2 * tig;
            const ushort_t* p1 = p0 + 8 * QS2;
            a[0] = *(const u32*)p0;       a[1] = *(const u32*)p1;
            a[2] = *(const u32*)(p0 + 8); a[3] = *(const u32*)(p1 + 8);
            #pragma unroll
            for (int nf = 0; nf < 8; nf++) {
                const ushort_t* q0 = Kb + (64 * wc + nf * 8 + g) * KS2 + k0 + 2 * tig;
                mma_bf16(eacc[nf], a, *(const u32*)q0, *(const u32*)(q0 + 8));
            }
        }
        int ra = 16 * wr + g, rb = ra + 8;
        float ca = crow[ra], cb = crow[rb];
        float* atta = att + (((size_t)(b * HH + h)) * SS + (i0 + ra)) * SS + j0;
        float* attb = att + (((size_t)(b * HH + h)) * SS + (i0 + rb)) * SS + j0;
        #pragma unroll
        for (int nf = 0; nf < 8; nf++) {
            int col = 64 * wc + 8 * nf + 2 * tig;
            float2 uj = *(const float2*)&usj[j0 + col];
            float4 e = eacc[nf];
            float t0 = uj.x * __expf(e.x * 0.125f);
            float t1 = uj.y * __expf(e.y * 0.125f);
            float t2 = uj.x * __expf(e.z * 0.125f);
            float t3 = uj.y * __expf(e.w * 0.125f);
            float f0 = __fdividef(t0, ca + t0);
            float f1 = __fdividef(t1, ca + t1);
            float f2 = __fdividef(t2, cb + t2);
            float f3 = __fdividef(t3, cb + t3);
            stcs2(atta + col, f0, f1);
            stcs2(attb + col, f2, f3);
            *(u32*)&Gs[ra * GS2 + col] = pack_bf16x2(1.f - f0, 1.f - f1);
            *(u32*)&Gs[rb * GS2 + col] = pack_bf16x2(1.f - f2, 1.f - f3);
        }
        __syncthreads();
        #pragma unroll
        for (int ks = 0; ks < 8; ks++) {
            int k0 = ks * 16;
            u32 a[4];
            const ushort_t* p0 = Gs + (16 * wr2 + g) * GS2 + k0 + 2 * tig;
            const ushort_t* p1 = p0 + 8 * GS2;
            a[0] = *(const u32*)p0;       a[1] = *(const u32*)p1;
            a[2] = *(const u32*)(p0 + 8); a[3] = *(const u32*)(p1 + 8);
            #pragma unroll
            for (int nf = 0; nf < 4; nf++) {
                const ushort_t* q0 = Vb + (32 * wc2 + nf * 8 + g) * VS2 + k0 + 2 * tig;
                mma_bf16(xacc[nf], a, *(const u32*)q0, *(const u32*)(q0 + 8));
            }
        }
    }

    // epilogue: x = colsum(V) - G@V
    {
        const float* vs = g_vsum + (b * HH + h) * HDD;
        int ra = 16 * wr2 + g, rb = ra + 8;
        #pragma unroll
        for (int nf = 0; nf < 4; nf++) {
            int col = 32 * wc2 + 8 * nf + 2 * tig;
            float2 v2 = *(const float2*)&vs[col];
            float4 xv = xacc[nf];
            float* xa = g_x + ((size_t)b * SS + i0 + ra) * DD + h * HDD + col;
            float* xb = g_x + ((size_t)b * SS + i0 + rb) * DD + h * HDD + col;
            *(float2*)xa = make_float2(v2.x - xv.x, v2.y - xv.y);
            *(float2*)xb = make_float2(v2.x - xv.z, v2.y - xv.w);
        }
    }
}

// ---------------- launch ----------------
extern "C" void kernel_launch(void* const* d_in, const int* in_sizes, int n_in,
                              void* d_out, int out_size) {
    const float* query = (const float*)d_in[0];
    const float* key   = (const float*)d_in[1];
    const float* value = (const float*)d_in[2];
    const float* u     = (const float*)d_in[3];
    const float* code  = (const float*)d_in[4];
    const float* W     = (const float*)d_in[5];
    const float* bias  = (const float*)d_in[6];

    TcParams tp;
    tp.code = code;
    for (int p = 0; p < 4; p++) {
        tp.wcw[p] = (const float*)d_in[7 + 4 * p];
        tp.wcb[p] = (const float*)d_in[8 + 4 * p];
        tp.lng[p] = (const float*)d_in[9 + 4 * p];
        tp.lnb[p] = (const float*)d_in[10 + 4 * p];
    }

    cudaFuncSetAttribute(gemm_mma_kernel, cudaFuncAttributeMaxDynamicSharedMemorySize,
                         GEMM_SMEM);
    cudaFuncSetAttribute(attn_mma_kernel, cudaFuncAttributeMaxDynamicSharedMemorySize,
                         AT_SMEM_BYTES);

    // 1) transformed codes
    tc_kernel<<<4, 256>>>(tp);
    // 2) split-bf16 conversions (tc folded into A operands; lo only for V)
    conv_in_kernel<<<dim3(BB * SS * DD / 4 / 256, 3), 256>>>(query, key, value);
    conv_w_kernel<<<DD * DD / 4 / 256, 256>>>(W);
    // 3) projections: Q,K 1-term; V 3-term
    gemm_mma_kernel<<<dim3(DD / 128, BB * SS / 128, 2), 256, GEMM_SMEM>>>(bias, nullptr, 0, 1);
    gemm_mma_kernel<<<dim3(DD / 128, BB * SS / 128, 1), 256, GEMM_SMEM>>>(bias, nullptr, 2, 3);
    // 4) colsum of V
    vsum_kernel<<<BB * HH, 512>>>();
    // 5) fused attention -> attention region of d_out (streaming) + g_x
    float* att = (float*)d_out + (size_t)BB * SS * DD;
    attn_mma_kernel<<<dim3(SS / 64, HH, BB), 256, AT_SMEM_BYTES>>>(u, att);
    // 6) split-convert x, then O-projection (3-term) -> x region of d_out
    conv_x_kernel<<<BB * SS * DD / 4 / 256, 256>>>();
    gemm_mma_kernel<<<dim3(DD / 128, BB * SS / 128, 1), 256, GEMM_SMEM>>>(bias, (float*)d_out, 3, 3);
}